// round 11
// baseline (speedup 1.0000x reference)
#include <cuda_runtime.h>
#include <cuda_fp16.h>
#include <math.h>

#define B_ 64
#define T_ 1024
#define D_ 512
#define U_ 1024
#define BT (B_ * T_)

// ---------------- device scratch (no allocation allowed) ----------------
__device__ __align__(128) __half g_fhi[BT * D_];   // 64 MB
__device__ __align__(128) __half g_w1t[U_ * D_];   // [n][k], 1 MB
__device__ float g_projh[B_ * U_];
__device__ float g_lpart[4][BT];   // per-n-quarter logit partials
__device__ float g_ws[BT];         // softmax weights

// ---------------- PTX helpers ----------------
__device__ __forceinline__ unsigned smem_u32(const void* p) {
    unsigned a;
    asm("{ .reg .u64 t; cvta.to.shared.u64 t, %1; cvt.u32.u64 %0, t; }"
        : "=r"(a) : "l"(p));
    return a;
}
__device__ __forceinline__ void cpa16(unsigned dst, const void* src) {
    asm volatile("cp.async.cg.shared.global [%0], [%1], 16;" :: "r"(dst), "l"(src));
}
__device__ __forceinline__ void cpa_commit() { asm volatile("cp.async.commit_group;"); }
__device__ __forceinline__ void ldsm4(unsigned addr, unsigned& r0, unsigned& r1,
                                      unsigned& r2, unsigned& r3) {
    asm volatile("ldmatrix.sync.aligned.m8n8.x4.shared.b16 {%0,%1,%2,%3}, [%4];"
                 : "=r"(r0), "=r"(r1), "=r"(r2), "=r"(r3) : "r"(addr));
}
__device__ __forceinline__ void mma16816(float* c, unsigned a0, unsigned a1,
                                         unsigned a2, unsigned a3,
                                         unsigned b0, unsigned b1) {
    asm volatile(
        "mma.sync.aligned.m16n8k16.row.col.f32.f16.f16.f32 "
        "{%0,%1,%2,%3}, {%4,%5,%6,%7}, {%8,%9}, {%0,%1,%2,%3};"
        : "+f"(c[0]), "+f"(c[1]), "+f"(c[2]), "+f"(c[3])
        : "r"(a0), "r"(a1), "r"(a2), "r"(a3), "r"(b0), "r"(b1));
}
// fast tanh: 1 - 2/(e^{2x}+1). abs err ~2e-7.
__device__ __forceinline__ float ftanh(float x) {
    float e = __expf(2.0f * x);
    return 1.0f - __fdividef(2.0f, e + 1.0f);
}

// ---------------- smem layout for score kernel ----------------
#define STAGE 49152            // A (128x64 fp16 = 16KB) + B (256x64 fp16 = 32KB)
#define OFF_BT 16384
#define OFF_PH 196608          // 256 floats
#define OFF_V  197632          // 256 floats
#define OFF_RED 198656         // 128 x 4 floats
#define SMEM_TOTAL 200704

// ---------------------------------------------------------------------------
// prep kernel: fused  fsplit (fp32->fp16 feat) + W1 transpose + proj_h GEMV
// ---------------------------------------------------------------------------
#define NF_BLK (BT * D_ / 4 / 256)   // 32768
#define NW_BLK 512                   // (U/32) x (D/32)
#define NP_BLK 32                    // (U/256) x (B/8)
__global__ void __launch_bounds__(256)
prep_kernel(const float* __restrict__ feat, const float* __restrict__ W1,
            const float* __restrict__ hidden, const float* __restrict__ W2,
            const float* __restrict__ W2b) {
    __shared__ __align__(16) char sbuf[16384];
    const int bid = blockIdx.x;
    const int tid = threadIdx.x;

    if (bid < NF_BLK) {
        long i = (long)bid * 256 + tid;
        float4 v = ((const float4*)feat)[i];
        uint2 hw;
        hw.x = (unsigned)__half_as_ushort(__float2half_rn(v.x)) |
               ((unsigned)__half_as_ushort(__float2half_rn(v.y)) << 16);
        hw.y = (unsigned)__half_as_ushort(__float2half_rn(v.z)) |
               ((unsigned)__half_as_ushort(__float2half_rn(v.w)) << 16);
        ((uint2*)g_fhi)[i] = hw;
    } else if (bid < NF_BLK + NW_BLK) {
        float (*tile)[33] = (float(*)[33])sbuf;
        const int wb = bid - NF_BLK;
        const int n0 = (wb & 31) * 32, k0 = (wb >> 5) * 32;
        const int tx = tid & 31, ty = tid >> 5;
        for (int r = ty; r < 32; r += 8)
            tile[r][tx] = W1[(size_t)(k0 + r) * U_ + n0 + tx];
        __syncthreads();
        for (int rr = ty; rr < 32; rr += 8)
            g_w1t[(size_t)(n0 + rr) * D_ + k0 + tx] = __float2half_rn(tile[tx][rr]);
    } else {
        float (*hs)[D_] = (float(*)[D_])sbuf;
        const int pb = bid - NF_BLK - NW_BLK;
        const int u = (pb & 3) * 256 + tid;
        const int b0 = (pb >> 2) * 8;
#pragma unroll
        for (int i = 0; i < 4; i++)
            ((float4*)hs)[tid + i * 256] =
                ((const float4*)(hidden + (size_t)b0 * D_))[tid + i * 256];
        __syncthreads();
        float acc[8];
#pragma unroll
        for (int i = 0; i < 8; i++) acc[i] = 0.f;
#pragma unroll 4
        for (int k = 0; k < D_; k++) {
            float w = W2[(size_t)k * U_ + u];
#pragma unroll
            for (int bb = 0; bb < 8; bb++) acc[bb] += hs[bb][k] * w;
        }
        float bias = W2b[u];
#pragma unroll
        for (int bb = 0; bb < 8; bb++)
            g_projh[(size_t)(b0 + bb) * U_ + u] = acc[bb] + bias;
    }
}

// ---------------------------------------------------------------------------
// score kernel: fp16 mma.sync GEMM, software-pipelined register fragments
// CTA tile 128(M) x 256(N), 8 K chunks of 64, 4-stage ring (distance 3)
// grid (4 n-quarters, BT/128), 256 threads (8 warps, 64x64 warp tiles)
// ---------------------------------------------------------------------------
__global__ void __launch_bounds__(256, 1)
score_kernel(const float* __restrict__ W1b, const float* __restrict__ Vw) {
    extern __shared__ __align__(1024) char smem[];
    const unsigned sbase = smem_u32(smem);
    const int tid = threadIdx.x;
    const int wid = tid >> 5, lid = tid & 31;
    const int wm = wid & 1, wn = wid >> 1;       // 2 x 4 warp grid, tile 64m x 64n
    const int nq = blockIdx.x;
    const int bt0 = blockIdx.y * 128;
    const int b = bt0 >> 10;
    const int n0 = nq * 256;
    float* shPh = (float*)(smem + OFF_PH);
    float* shV  = (float*)(smem + OFF_V);
    float (*red)[4] = (float(*)[4])(smem + OFF_RED);

    shPh[tid] = g_projh[(size_t)b * U_ + n0 + tid] + W1b[n0 + tid];
    shV[tid]  = Vw[n0 + tid];

    // loop-invariant cp.async offsets (row step 32 preserves row&7)
    unsigned a_src0, a_dst0, b_src0, b_dst0;
    {
        int row = tid >> 3, c16 = tid & 7;
        a_src0 = (unsigned)((bt0 + row) * D_ + c16 * 8);
        a_dst0 = row * 128 + ((c16 ^ (row & 7)) * 16);
        b_src0 = (unsigned)((n0 + row) * D_ + c16 * 8);
        b_dst0 = OFF_BT + row * 128 + ((c16 ^ (row & 7)) * 16);
    }

    // loop-invariant ldmatrix bases (k-step enters via XOR of kk*32)
    const int lrow = lid & 15;
    const int lch  = lid >> 4;
    unsigned abase0, bbase0;
    {
        int row = wm * 64 + lrow;
        abase0 = row * 128 + ((lch ^ (row & 7)) * 16);
        int rowb = wn * 64 + lrow;
        bbase0 = OFF_BT + rowb * 128 + ((lch ^ (rowb & 7)) * 16);
    }

    float Cr[4][8][4];
#pragma unroll
    for (int mt = 0; mt < 4; mt++)
#pragma unroll
        for (int nt = 0; nt < 8; nt++)
#pragma unroll
            for (int j = 0; j < 4; j++) Cr[mt][nt][j] = 0.f;

    // prologue: chunks 0..2 into stages 0..2
#pragma unroll
    for (int c = 0; c < 3; c++) {
        const int k0 = c * 64;
        const unsigned stg = sbase + c * STAGE;
#pragma unroll
        for (int i = 0; i < 4; i++)
            cpa16(stg + a_dst0 + i * 4096, g_fhi + k0 + a_src0 + i * 16384);
#pragma unroll
        for (int i = 0; i < 8; i++)
            cpa16(stg + b_dst0 + i * 4096, g_w1t + k0 + b_src0 + i * 16384);
        cpa_commit();
    }

    for (int c = 0; c < 8; c++) {
        asm volatile("cp.async.wait_group 2;" ::: "memory");
        __syncthreads();
        if (c + 3 < 8) {
            const int k0 = (c + 3) * 64;
            const unsigned stg = sbase + ((c + 3) & 3) * STAGE;
#pragma unroll
            for (int i = 0; i < 4; i++)
                cpa16(stg + a_dst0 + i * 4096, g_fhi + k0 + a_src0 + i * 16384);
#pragma unroll
            for (int i = 0; i < 8; i++)
                cpa16(stg + b_dst0 + i * 4096, g_w1t + k0 + b_src0 + i * 16384);
        }
        cpa_commit();

        const unsigned Ab = sbase + (c & 3) * STAGE;
        // double-buffered fragments: load kk, compute kk-1
        unsigned ah[2][4][4], bm[2][4][4];
#pragma unroll
        for (int np = 0; np < 4; np++)
            ldsm4(Ab + (bbase0 + np * 2048),
                  bm[0][np][0], bm[0][np][1], bm[0][np][2], bm[0][np][3]);
#pragma unroll
        for (int mt = 0; mt < 4; mt++)
            ldsm4(Ab + (abase0 + mt * 2048),
                  ah[0][mt][0], ah[0][mt][1], ah[0][mt][2], ah[0][mt][3]);
#pragma unroll
        for (int kk = 0; kk < 4; kk++) {
            const int cur = kk & 1, nxt = cur ^ 1;
            if (kk < 3) {
                const unsigned kx = (unsigned)(kk + 1) << 5;
#pragma unroll
                for (int np = 0; np < 4; np++)
                    ldsm4(Ab + ((bbase0 + np * 2048) ^ kx),
                          bm[nxt][np][0], bm[nxt][np][1], bm[nxt][np][2], bm[nxt][np][3]);
#pragma unroll
                for (int mt = 0; mt < 4; mt++)
                    ldsm4(Ab + ((abase0 + mt * 2048) ^ kx),
                          ah[nxt][mt][0], ah[nxt][mt][1], ah[nxt][mt][2], ah[nxt][mt][3]);
            }
#pragma unroll
            for (int mt = 0; mt < 4; mt++)
#pragma unroll
                for (int nt = 0; nt < 8; nt++) {
                    const int np = nt >> 1, od = nt & 1;
                    mma16816(Cr[mt][nt],
                             ah[cur][mt][0], ah[cur][mt][1], ah[cur][mt][2], ah[cur][mt][3],
                             bm[cur][np][od], bm[cur][np][od + 2]);
                }
        }
    }

    // ---- epilogue: fast tanh + V-dot on fragments ----
    float p0[4], p1[4];
#pragma unroll
    for (int mt = 0; mt < 4; mt++) { p0[mt] = 0.f; p1[mt] = 0.f; }
#pragma unroll
    for (int mt = 0; mt < 4; mt++)
#pragma unroll
        for (int nt = 0; nt < 8; nt++) {
            int nc = wn * 64 + nt * 8 + (lid & 3) * 2;
            float ph0 = shPh[nc], ph1 = shPh[nc + 1];
            float v0 = shV[nc], v1 = shV[nc + 1];
            p0[mt] += ftanh(Cr[mt][nt][0] + ph0) * v0
                    + ftanh(Cr[mt][nt][1] + ph1) * v1;
            p1[mt] += ftanh(Cr[mt][nt][2] + ph0) * v0
                    + ftanh(Cr[mt][nt][3] + ph1) * v1;
        }
#pragma unroll
    for (int mt = 0; mt < 4; mt++) {
        p0[mt] += __shfl_xor_sync(0xFFFFFFFFu, p0[mt], 1);
        p0[mt] += __shfl_xor_sync(0xFFFFFFFFu, p0[mt], 2);
        p1[mt] += __shfl_xor_sync(0xFFFFFFFFu, p1[mt], 1);
        p1[mt] += __shfl_xor_sync(0xFFFFFFFFu, p1[mt], 2);
    }
    if ((lid & 3) == 0) {
#pragma unroll
        for (int mt = 0; mt < 4; mt++) {
            int rl = wm * 64 + mt * 16 + (lid >> 2);
            red[rl][wn] = p0[mt];
            red[rl + 8][wn] = p1[mt];
        }
    }
    __syncthreads();
    if (tid < 128) {
        float s = red[tid][0] + red[tid][1] + red[tid][2] + red[tid][3];
        g_lpart[nq][bt0 + tid] = s;
    }
}

// ---------------------------------------------------------------------------
// softmax over T: grid B_, 256 threads; writes weights to g_ws + output
// ---------------------------------------------------------------------------
__global__ void softmax_w_kernel(const float* __restrict__ Vb,
                                 float* __restrict__ out) {
    __shared__ float rbuf[8];
    const int b = blockIdx.x;
    const int tid = threadIdx.x;
    const int wid = tid >> 5, lid = tid & 31;
    const float vb = Vb[0];

    float l[4];
    float mx = -1e30f;
#pragma unroll
    for (int i = 0; i < 4; i++) {
        int idx = b * T_ + tid * 4 + i;
        l[i] = g_lpart[0][idx] + g_lpart[1][idx] + g_lpart[2][idx] + g_lpart[3][idx] + vb;
        mx = fmaxf(mx, l[i]);
    }
#pragma unroll
    for (int s = 16; s > 0; s >>= 1) mx = fmaxf(mx, __shfl_xor_sync(~0u, mx, s));
    if (lid == 0) rbuf[wid] = mx;
    __syncthreads();
    float m8 = rbuf[lid & 7];
#pragma unroll
    for (int s = 4; s > 0; s >>= 1) m8 = fmaxf(m8, __shfl_xor_sync(~0u, m8, s));
    mx = __shfl_sync(~0u, m8, 0);

    float ssum = 0.f;
#pragma unroll
    for (int i = 0; i < 4; i++) {
        l[i] = expf(l[i] - mx);
        ssum += l[i];
    }
#pragma unroll
    for (int s = 16; s > 0; s >>= 1) ssum += __shfl_xor_sync(~0u, ssum, s);
    __syncthreads();
    if (lid == 0) rbuf[wid] = ssum;
    __syncthreads();
    float s8 = rbuf[lid & 7];
#pragma unroll
    for (int s = 4; s > 0; s >>= 1) s8 += __shfl_xor_sync(~0u, s8, s);
    const float inv = 1.0f / __shfl_sync(~0u, s8, 0);

    float4 w4 = make_float4(l[0] * inv, l[1] * inv, l[2] * inv, l[3] * inv);
    ((float4*)(g_ws + b * T_))[tid] = w4;
    ((float4*)(out + B_ * D_ + b * T_))[tid] = w4;
}

// ---------------------------------------------------------------------------
// context vector: grid (B_, D/128), 512 threads (4 T-quarters x 128 d-lanes)
// ---------------------------------------------------------------------------
__global__ void __launch_bounds__(512)
ctx_kernel(float* __restrict__ out) {
    __shared__ float ws[T_];
    __shared__ float red[4][128];
    const int b = blockIdx.x;
    const int d0 = blockIdx.y * 128;
    const int tid = threadIdx.x;
    const int dl = tid & 127;
    const int tq = tid >> 7;

    ((float2*)ws)[tid] = ((const float2*)(g_ws + b * T_))[tid];
    __syncthreads();

    const __half* fb = g_fhi + (size_t)b * T_ * D_ + (size_t)tq * 256 * D_ + d0 + dl;
    const float* wq = ws + tq * 256;
    float acc = 0.f;
#pragma unroll 8
    for (int t = 0; t < 256; t++) acc += wq[t] * __half2float(fb[(size_t)t * D_]);
    red[tq][dl] = acc;
    __syncthreads();
    if (tid < 128)
        out[b * D_ + d0 + tid] = red[0][tid] + red[1][tid] + red[2][tid] + red[3][tid];
}

// ---------------------------------------------------------------------------
extern "C" void kernel_launch(void* const* d_in, const int* in_sizes, int n_in,
                              void* d_out, int out_size) {
    const float* feat   = (const float*)d_in[0];
    const float* hidden = (const float*)d_in[1];
    const float* W1w    = (const float*)d_in[2];
    const float* W1b    = (const float*)d_in[3];
    const float* W2w    = (const float*)d_in[4];
    const float* W2b    = (const float*)d_in[5];
    const float* Vw     = (const float*)d_in[6];
    const float* Vb     = (const float*)d_in[7];
    float* out = (float*)d_out;

    static bool attr_set = false;
    if (!attr_set) {
        cudaFuncSetAttribute(score_kernel, cudaFuncAttributeMaxDynamicSharedMemorySize,
                             SMEM_TOTAL);
        attr_set = true;
    }

    prep_kernel<<<NF_BLK + NW_BLK + NP_BLK, 256>>>(feat, W1w, hidden, W2w, W2b);
    score_kernel<<<dim3(4, BT / 128), 256, SMEM_TOTAL>>>(W1b, Vw);
    softmax_w_kernel<<<B_, 256>>>(Vb, out);
    ctx_kernel<<<dim3(B_, D_ / 128), 512>>>(out);
}

// round 12
// speedup vs baseline: 1.0814x; 1.0814x over previous
#include <cuda_runtime.h>
#include <cuda_fp16.h>
#include <math.h>

#define B_ 64
#define T_ 1024
#define D_ 512
#define U_ 1024
#define BT (B_ * T_)

// ---------------- device scratch (no allocation allowed) ----------------
__device__ __align__(128) __half g_fhi[BT * D_];   // 64 MB
__device__ __align__(128) __half g_w1t[U_ * D_];   // [n][k], 1 MB
__device__ float g_projh[B_ * U_];
__device__ float g_lpart[8][BT];   // per-n-eighth logit partials
__device__ float g_ws[BT];         // softmax weights

// ---------------- PTX helpers ----------------
__device__ __forceinline__ unsigned smem_u32(const void* p) {
    unsigned a;
    asm("{ .reg .u64 t; cvta.to.shared.u64 t, %1; cvt.u32.u64 %0, t; }"
        : "=r"(a) : "l"(p));
    return a;
}
__device__ __forceinline__ void cpa16(unsigned dst, const void* src) {
    asm volatile("cp.async.cg.shared.global [%0], [%1], 16;" :: "r"(dst), "l"(src));
}
__device__ __forceinline__ void cpa_commit() { asm volatile("cp.async.commit_group;"); }
__device__ __forceinline__ void ldsm4(unsigned addr, unsigned& r0, unsigned& r1,
                                      unsigned& r2, unsigned& r3) {
    asm volatile("ldmatrix.sync.aligned.m8n8.x4.shared.b16 {%0,%1,%2,%3}, [%4];"
                 : "=r"(r0), "=r"(r1), "=r"(r2), "=r"(r3) : "r"(addr));
}
__device__ __forceinline__ void mma16816(float* c, unsigned a0, unsigned a1,
                                         unsigned a2, unsigned a3,
                                         unsigned b0, unsigned b1) {
    asm volatile(
        "mma.sync.aligned.m16n8k16.row.col.f32.f16.f16.f32 "
        "{%0,%1,%2,%3}, {%4,%5,%6,%7}, {%8,%9}, {%0,%1,%2,%3};"
        : "+f"(c[0]), "+f"(c[1]), "+f"(c[2]), "+f"(c[3])
        : "r"(a0), "r"(a1), "r"(a2), "r"(a3), "r"(b0), "r"(b1));
}
// fast tanh: 1 - 2/(e^{2x}+1). abs err ~2e-7.
__device__ __forceinline__ float ftanh(float x) {
    float e = __expf(2.0f * x);
    return 1.0f - __fdividef(2.0f, e + 1.0f);
}

// ---------------- smem layout for score kernel (2 CTAs/SM) ----------------
#define STAGE 32768            // A (128x64 fp16 = 16KB) + B (128x64 fp16 = 16KB)
#define OFF_BT 16384
#define OFF_PH 98304           // 128 floats
#define OFF_V  98816           // 128 floats
#define OFF_RED 99328          // 128 x 4 floats
#define SMEM_TOTAL 101376

// ---------------------------------------------------------------------------
// prep kernel: fused  fsplit (fp32->fp16 feat) + W1 transpose + proj_h GEMV
// ---------------------------------------------------------------------------
#define NF_BLK (BT * D_ / 4 / 256)   // 32768
#define NW_BLK 512                   // (U/32) x (D/32)
#define NP_BLK 32                    // (U/256) x (B/8)
__global__ void __launch_bounds__(256)
prep_kernel(const float* __restrict__ feat, const float* __restrict__ W1,
            const float* __restrict__ hidden, const float* __restrict__ W2,
            const float* __restrict__ W2b) {
    __shared__ __align__(16) char sbuf[16384];
    const int bid = blockIdx.x;
    const int tid = threadIdx.x;

    if (bid < NF_BLK) {
        long i = (long)bid * 256 + tid;
        float4 v = ((const float4*)feat)[i];
        uint2 hw;
        hw.x = (unsigned)__half_as_ushort(__float2half_rn(v.x)) |
               ((unsigned)__half_as_ushort(__float2half_rn(v.y)) << 16);
        hw.y = (unsigned)__half_as_ushort(__float2half_rn(v.z)) |
               ((unsigned)__half_as_ushort(__float2half_rn(v.w)) << 16);
        ((uint2*)g_fhi)[i] = hw;
    } else if (bid < NF_BLK + NW_BLK) {
        float (*tile)[33] = (float(*)[33])sbuf;
        const int wb = bid - NF_BLK;
        const int n0 = (wb & 31) * 32, k0 = (wb >> 5) * 32;
        const int tx = tid & 31, ty = tid >> 5;
        for (int r = ty; r < 32; r += 8)
            tile[r][tx] = W1[(size_t)(k0 + r) * U_ + n0 + tx];
        __syncthreads();
        for (int rr = ty; rr < 32; rr += 8)
            g_w1t[(size_t)(n0 + rr) * D_ + k0 + tx] = __float2half_rn(tile[tx][rr]);
    } else {
        float (*hs)[D_] = (float(*)[D_])sbuf;
        const int pb = bid - NF_BLK - NW_BLK;
        const int u = (pb & 3) * 256 + tid;
        const int b0 = (pb >> 2) * 8;
#pragma unroll
        for (int i = 0; i < 4; i++)
            ((float4*)hs)[tid + i * 256] =
                ((const float4*)(hidden + (size_t)b0 * D_))[tid + i * 256];
        __syncthreads();
        float acc[8];
#pragma unroll
        for (int i = 0; i < 8; i++) acc[i] = 0.f;
#pragma unroll 4
        for (int k = 0; k < D_; k++) {
            float w = W2[(size_t)k * U_ + u];
#pragma unroll
            for (int bb = 0; bb < 8; bb++) acc[bb] += hs[bb][k] * w;
        }
        float bias = W2b[u];
#pragma unroll
        for (int bb = 0; bb < 8; bb++)
            g_projh[(size_t)(b0 + bb) * U_ + u] = acc[bb] + bias;
    }
}

// ---------------------------------------------------------------------------
// score kernel: fp16 mma.sync GEMM + fast-tanh + V-dot epilogue
// CTA tile 128(M) x 128(N), 8 K chunks of 64
// 3-stage ring, prefetch distance 2 (R8-proven); 2 CTAs/SM for bubble hiding
// grid (8 n-eighths, BT/128), 256 threads (8 warps 2x4, warp tile 64x32)
// ---------------------------------------------------------------------------
__global__ void __launch_bounds__(256, 2)
score_kernel(const float* __restrict__ W1b, const float* __restrict__ Vw) {
    extern __shared__ __align__(1024) char smem[];
    const unsigned sbase = smem_u32(smem);
    const int tid = threadIdx.x;
    const int wid = tid >> 5, lid = tid & 31;
    const int wm = wid & 1, wn = wid >> 1;       // 2 x 4 warp grid, tile 64m x 32n
    const int nq = blockIdx.x;
    const int bt0 = blockIdx.y * 128;
    const int b = bt0 >> 10;
    const int n0 = nq * 128;
    float* shPh = (float*)(smem + OFF_PH);
    float* shV  = (float*)(smem + OFF_V);
    float (*red)[4] = (float(*)[4])(smem + OFF_RED);

    if (tid < 128) {
        shPh[tid] = g_projh[(size_t)b * U_ + n0 + tid] + W1b[n0 + tid];
        shV[tid]  = Vw[n0 + tid];
    }

    // loop-invariant cp.async offsets (row step 32 preserves row&7)
    unsigned a_src0, a_dst0, b_src0, b_dst0;
    {
        int row = tid >> 3, c16 = tid & 7;
        a_src0 = (unsigned)((bt0 + row) * D_ + c16 * 8);
        a_dst0 = row * 128 + ((c16 ^ (row & 7)) * 16);
        b_src0 = (unsigned)((n0 + row) * D_ + c16 * 8);
        b_dst0 = OFF_BT + row * 128 + ((c16 ^ (row & 7)) * 16);
    }

    // loop-invariant ldmatrix bases (k-step enters via XOR of kk*32)
    const int lrow = lid & 15;
    const int lch  = lid >> 4;
    unsigned abase0, bbase0;
    {
        int row = wm * 64 + lrow;
        abase0 = row * 128 + ((lch ^ (row & 7)) * 16);
        int rowb = wn * 32 + lrow;
        bbase0 = OFF_BT + rowb * 128 + ((lch ^ (rowb & 7)) * 16);
    }

    float Cr[4][4][4];
#pragma unroll
    for (int mt = 0; mt < 4; mt++)
#pragma unroll
        for (int nt = 0; nt < 4; nt++)
#pragma unroll
            for (int j = 0; j < 4; j++) Cr[mt][nt][j] = 0.f;

    // prologue: chunks 0,1 into stages 0,1
#pragma unroll
    for (int c = 0; c < 2; c++) {
        const int k0 = c * 64;
        const unsigned stg = sbase + c * STAGE;
#pragma unroll
        for (int i = 0; i < 4; i++)
            cpa16(stg + a_dst0 + i * 4096, g_fhi + k0 + a_src0 + i * 16384);
#pragma unroll
        for (int i = 0; i < 4; i++)
            cpa16(stg + b_dst0 + i * 4096, g_w1t + k0 + b_src0 + i * 16384);
        cpa_commit();
    }

    for (int c = 0; c < 8; c++) {
        asm volatile("cp.async.wait_group 1;" ::: "memory");
        __syncthreads();   // frees stage (c-1)%3 == (c+2)%3 for rewrite
        if (c + 2 < 8) {
            const int k0 = (c + 2) * 64;
            const unsigned stg = sbase + ((c + 2) % 3) * STAGE;
#pragma unroll
            for (int i = 0; i < 4; i++)
                cpa16(stg + a_dst0 + i * 4096, g_fhi + k0 + a_src0 + i * 16384);
#pragma unroll
            for (int i = 0; i < 4; i++)
                cpa16(stg + b_dst0 + i * 4096, g_w1t + k0 + b_src0 + i * 16384);
        }
        cpa_commit();   // exactly one group per iteration keeps accounting exact

        const unsigned Ab = sbase + (c % 3) * STAGE;
#pragma unroll
        for (int kk = 0; kk < 4; kk++) {
            const unsigned kx = kk << 5;
            unsigned bf[4][2];
#pragma unroll
            for (int np = 0; np < 2; np++) {
                unsigned t0, t1, t2, t3;
                ldsm4(Ab + ((bbase0 + np * 2048) ^ kx), t0, t1, t2, t3);
                bf[np * 2][0] = t0; bf[np * 2][1] = t2;
                bf[np * 2 + 1][0] = t1; bf[np * 2 + 1][1] = t3;
            }
            unsigned ah[4][4];
#pragma unroll
            for (int mt = 0; mt < 4; mt++)
                ldsm4(Ab + ((abase0 + mt * 2048) ^ kx),
                      ah[mt][0], ah[mt][1], ah[mt][2], ah[mt][3]);
#pragma unroll
            for (int mt = 0; mt < 4; mt++)
#pragma unroll
                for (int nt = 0; nt < 4; nt++)
                    mma16816(Cr[mt][nt], ah[mt][0], ah[mt][1], ah[mt][2], ah[mt][3],
                             bf[nt][0], bf[nt][1]);
        }
    }

    // ---- epilogue: fast tanh + V-dot on fragments ----
    float p0[4], p1[4];
#pragma unroll
    for (int mt = 0; mt < 4; mt++) { p0[mt] = 0.f; p1[mt] = 0.f; }
#pragma unroll
    for (int mt = 0; mt < 4; mt++)
#pragma unroll
        for (int nt = 0; nt < 4; nt++) {
            int nc = wn * 32 + nt * 8 + (lid & 3) * 2;
            float ph0 = shPh[nc], ph1 = shPh[nc + 1];
            float v0 = shV[nc], v1 = shV[nc + 1];
            p0[mt] += ftanh(Cr[mt][nt][0] + ph0) * v0
                    + ftanh(Cr[mt][nt][1] + ph1) * v1;
            p1[mt] += ftanh(Cr[mt][nt][2] + ph0) * v0
                    + ftanh(Cr[mt][nt][3] + ph1) * v1;
        }
#pragma unroll
    for (int mt = 0; mt < 4; mt++) {
        p0[mt] += __shfl_xor_sync(0xFFFFFFFFu, p0[mt], 1);
        p0[mt] += __shfl_xor_sync(0xFFFFFFFFu, p0[mt], 2);
        p1[mt] += __shfl_xor_sync(0xFFFFFFFFu, p1[mt], 1);
        p1[mt] += __shfl_xor_sync(0xFFFFFFFFu, p1[mt], 2);
    }
    if ((lid & 3) == 0) {
#pragma unroll
        for (int mt = 0; mt < 4; mt++) {
            int rl = wm * 64 + mt * 16 + (lid >> 2);
            red[rl][wn] = p0[mt];
            red[rl + 8][wn] = p1[mt];
        }
    }
    __syncthreads();
    if (tid < 128) {
        float s = red[tid][0] + red[tid][1] + red[tid][2] + red[tid][3];
        g_lpart[nq][bt0 + tid] = s;
    }
}

// ---------------------------------------------------------------------------
// softmax over T: grid B_, 256 threads; writes weights to g_ws + output
// ---------------------------------------------------------------------------
__global__ void softmax_w_kernel(const float* __restrict__ Vb,
                                 float* __restrict__ out) {
    __shared__ float rbuf[8];
    const int b = blockIdx.x;
    const int tid = threadIdx.x;
    const int wid = tid >> 5, lid = tid & 31;
    const float vb = Vb[0];

    float l[4];
    float mx = -1e30f;
#pragma unroll
    for (int i = 0; i < 4; i++) {
        int idx = b * T_ + tid * 4 + i;
        float s = vb;
#pragma unroll
        for (int q = 0; q < 8; q++) s += g_lpart[q][idx];
        l[i] = s;
        mx = fmaxf(mx, l[i]);
    }
#pragma unroll
    for (int s = 16; s > 0; s >>= 1) mx = fmaxf(mx, __shfl_xor_sync(~0u, mx, s));
    if (lid == 0) rbuf[wid] = mx;
    __syncthreads();
    float m8 = rbuf[lid & 7];
#pragma unroll
    for (int s = 4; s > 0; s >>= 1) m8 = fmaxf(m8, __shfl_xor_sync(~0u, m8, s));
    mx = __shfl_sync(~0u, m8, 0);

    float ssum = 0.f;
#pragma unroll
    for (int i = 0; i < 4; i++) {
        l[i] = expf(l[i] - mx);
        ssum += l[i];
    }
#pragma unroll
    for (int s = 16; s > 0; s >>= 1) ssum += __shfl_xor_sync(~0u, ssum, s);
    __syncthreads();
    if (lid == 0) rbuf[wid] = ssum;
    __syncthreads();
    float s8 = rbuf[lid & 7];
#pragma unroll
    for (int s = 4; s > 0; s >>= 1) s8 += __shfl_xor_sync(~0u, s8, s);
    const float inv = 1.0f / __shfl_sync(~0u, s8, 0);

    float4 w4 = make_float4(l[0] * inv, l[1] * inv, l[2] * inv, l[3] * inv);
    ((float4*)(g_ws + b * T_))[tid] = w4;
    ((float4*)(out + B_ * D_ + b * T_))[tid] = w4;
}

// ---------------------------------------------------------------------------
// context vector: grid (B_, D/128), 512 threads (4 T-quarters x 128 d-lanes)
// ---------------------------------------------------------------------------
__global__ void __launch_bounds__(512)
ctx_kernel(float* __restrict__ out) {
    __shared__ float ws[T_];
    __shared__ float red[4][128];
    const int b = blockIdx.x;
    const int d0 = blockIdx.y * 128;
    const int tid = threadIdx.x;
    const int dl = tid & 127;
    const int tq = tid >> 7;

    ((float2*)ws)[tid] = ((const float2*)(g_ws + b * T_))[tid];
    __syncthreads();

    const __half* fb = g_fhi + (size_t)b * T_ * D_ + (size_t)tq * 256 * D_ + d0 + dl;
    const float* wq = ws + tq * 256;
    float acc = 0.f;
#pragma unroll 8
    for (int t = 0; t < 256; t++) acc += wq[t] * __half2float(fb[(size_t)t * D_]);
    red[tq][dl] = acc;
    __syncthreads();
    if (tid < 128)
        out[b * D_ + d0 + tid] = red[0][tid] + red[1][tid] + red[2][tid] + red[3][tid];
}

// ---------------------------------------------------------------------------
extern "C" void kernel_launch(void* const* d_in, const int* in_sizes, int n_in,
                              void* d_out, int out_size) {
    const float* feat   = (const float*)d_in[0];
    const float* hidden = (const float*)d_in[1];
    const float* W1w    = (const float*)d_in[2];
    const float* W1b    = (const float*)d_in[3];
    const float* W2w    = (const float*)d_in[4];
    const float* W2b    = (const float*)d_in[5];
    const float* Vw     = (const float*)d_in[6];
    const float* Vb     = (const float*)d_in[7];
    float* out = (float*)d_out;

    static bool attr_set = false;
    if (!attr_set) {
        cudaFuncSetAttribute(score_kernel, cudaFuncAttributeMaxDynamicSharedMemorySize,
                             SMEM_TOTAL);
        attr_set = true;
    }

    prep_kernel<<<NF_BLK + NW_BLK + NP_BLK, 256>>>(feat, W1w, hidden, W2w, W2b);
    score_kernel<<<dim3(8, BT / 128), 256, SMEM_TOTAL>>>(W1b, Vw);
    softmax_w_kernel<<<B_, 256>>>(Vb, out);
    ctx_kernel<<<dim3(B_, D_ / 128), 512>>>(out);
}

// round 13
// speedup vs baseline: 1.1089x; 1.0254x over previous
#include <cuda_runtime.h>
#include <cuda_fp16.h>
#include <math.h>

#define B_ 64
#define T_ 1024
#define D_ 512
#define U_ 1024
#define BT (B_ * T_)

// ---------------- device scratch (no allocation allowed) ----------------
__device__ __align__(128) __half g_fhi[BT * D_];   // 64 MB
__device__ __align__(128) __half g_w1t[U_ * D_];   // [n][k], 1 MB
__device__ float g_projh[B_ * U_];
__device__ float g_lpart[8][BT];   // per-n-eighth logit partials
__device__ float g_ws[BT];         // softmax weights

// ---------------- PTX helpers ----------------
__device__ __forceinline__ unsigned smem_u32(const void* p) {
    unsigned a;
    asm("{ .reg .u64 t; cvta.to.shared.u64 t, %1; cvt.u32.u64 %0, t; }"
        : "=r"(a) : "l"(p));
    return a;
}
__device__ __forceinline__ void cpa16(unsigned dst, const void* src) {
    asm volatile("cp.async.cg.shared.global [%0], [%1], 16;" :: "r"(dst), "l"(src));
}
__device__ __forceinline__ void cpa_commit() { asm volatile("cp.async.commit_group;"); }
__device__ __forceinline__ void ldsm4(unsigned addr, unsigned& r0, unsigned& r1,
                                      unsigned& r2, unsigned& r3) {
    asm volatile("ldmatrix.sync.aligned.m8n8.x4.shared.b16 {%0,%1,%2,%3}, [%4];"
                 : "=r"(r0), "=r"(r1), "=r"(r2), "=r"(r3) : "r"(addr));
}
__device__ __forceinline__ void mma16816(float* c, unsigned a0, unsigned a1,
                                         unsigned a2, unsigned a3,
                                         unsigned b0, unsigned b1) {
    asm volatile(
        "mma.sync.aligned.m16n8k16.row.col.f32.f16.f16.f32 "
        "{%0,%1,%2,%3}, {%4,%5,%6,%7}, {%8,%9}, {%0,%1,%2,%3};"
        : "+f"(c[0]), "+f"(c[1]), "+f"(c[2]), "+f"(c[3])
        : "r"(a0), "r"(a1), "r"(a2), "r"(a3), "r"(b0), "r"(b1));
}
// fast tanh: 1 - 2/(e^{2x}+1). abs err ~2e-7.
__device__ __forceinline__ float ftanh(float x) {
    float e = __expf(2.0f * x);
    return 1.0f - __fdividef(2.0f, e + 1.0f);
}

// ---------------- smem layout for score kernel (2 CTAs/SM) ----------------
#define STAGE 32768            // A (128x64 fp16 = 16KB) + B (128x64 fp16 = 16KB)
#define OFF_BT 16384
#define OFF_PH 98304           // 128 floats
#define OFF_V  98816           // 128 floats
#define OFF_RED 99328          // 128 x 4 floats
#define SMEM_TOTAL 101376

// ---------------------------------------------------------------------------
// prep kernel: fused  fsplit (fp32->fp16 feat) + W1 transpose + proj_h GEMV
// ---------------------------------------------------------------------------
#define NF_BLK (BT * D_ / 4 / 256)   // 32768
#define NW_BLK 512                   // (U/32) x (D/32)
#define NP_BLK 32                    // (U/256) x (B/8)
__global__ void __launch_bounds__(256)
prep_kernel(const float* __restrict__ feat, const float* __restrict__ W1,
            const float* __restrict__ hidden, const float* __restrict__ W2,
            const float* __restrict__ W2b) {
    __shared__ __align__(16) char sbuf[16384];
    const int bid = blockIdx.x;
    const int tid = threadIdx.x;

    if (bid < NF_BLK) {
        long i = (long)bid * 256 + tid;
        float4 v = ((const float4*)feat)[i];
        uint2 hw;
        hw.x = (unsigned)__half_as_ushort(__float2half_rn(v.x)) |
               ((unsigned)__half_as_ushort(__float2half_rn(v.y)) << 16);
        hw.y = (unsigned)__half_as_ushort(__float2half_rn(v.z)) |
               ((unsigned)__half_as_ushort(__float2half_rn(v.w)) << 16);
        ((uint2*)g_fhi)[i] = hw;
    } else if (bid < NF_BLK + NW_BLK) {
        float (*tile)[33] = (float(*)[33])sbuf;
        const int wb = bid - NF_BLK;
        const int n0 = (wb & 31) * 32, k0 = (wb >> 5) * 32;
        const int tx = tid & 31, ty = tid >> 5;
        for (int r = ty; r < 32; r += 8)
            tile[r][tx] = W1[(size_t)(k0 + r) * U_ + n0 + tx];
        __syncthreads();
        for (int rr = ty; rr < 32; rr += 8)
            g_w1t[(size_t)(n0 + rr) * D_ + k0 + tx] = __float2half_rn(tile[tx][rr]);
    } else {
        float (*hs)[D_] = (float(*)[D_])sbuf;
        const int pb = bid - NF_BLK - NW_BLK;
        const int u = (pb & 3) * 256 + tid;
        const int b0 = (pb >> 2) * 8;
#pragma unroll
        for (int i = 0; i < 4; i++)
            ((float4*)hs)[tid + i * 256] =
                ((const float4*)(hidden + (size_t)b0 * D_))[tid + i * 256];
        __syncthreads();
        float acc[8];
#pragma unroll
        for (int i = 0; i < 8; i++) acc[i] = 0.f;
#pragma unroll 4
        for (int k = 0; k < D_; k++) {
            float w = W2[(size_t)k * U_ + u];
#pragma unroll
            for (int bb = 0; bb < 8; bb++) acc[bb] += hs[bb][k] * w;
        }
        float bias = W2b[u];
#pragma unroll
        for (int bb = 0; bb < 8; bb++)
            g_projh[(size_t)(b0 + bb) * U_ + u] = acc[bb] + bias;
    }
}

// ---------------------------------------------------------------------------
// score kernel: fp16 mma.sync GEMM + fast-tanh + V-dot epilogue
// (unchanged from R12 — 2 CTAs/SM win)
// ---------------------------------------------------------------------------
__global__ void __launch_bounds__(256, 2)
score_kernel(const float* __restrict__ W1b, const float* __restrict__ Vw) {
    extern __shared__ __align__(1024) char smem[];
    const unsigned sbase = smem_u32(smem);
    const int tid = threadIdx.x;
    const int wid = tid >> 5, lid = tid & 31;
    const int wm = wid & 1, wn = wid >> 1;       // 2 x 4 warp grid, tile 64m x 32n
    const int nq = blockIdx.x;
    const int bt0 = blockIdx.y * 128;
    const int b = bt0 >> 10;
    const int n0 = nq * 128;
    float* shPh = (float*)(smem + OFF_PH);
    float* shV  = (float*)(smem + OFF_V);
    float (*red)[4] = (float(*)[4])(smem + OFF_RED);

    if (tid < 128) {
        shPh[tid] = g_projh[(size_t)b * U_ + n0 + tid] + W1b[n0 + tid];
        shV[tid]  = Vw[n0 + tid];
    }

    unsigned a_src0, a_dst0, b_src0, b_dst0;
    {
        int row = tid >> 3, c16 = tid & 7;
        a_src0 = (unsigned)((bt0 + row) * D_ + c16 * 8);
        a_dst0 = row * 128 + ((c16 ^ (row & 7)) * 16);
        b_src0 = (unsigned)((n0 + row) * D_ + c16 * 8);
        b_dst0 = OFF_BT + row * 128 + ((c16 ^ (row & 7)) * 16);
    }

    const int lrow = lid & 15;
    const int lch  = lid >> 4;
    unsigned abase0, bbase0;
    {
        int row = wm * 64 + lrow;
        abase0 = row * 128 + ((lch ^ (row & 7)) * 16);
        int rowb = wn * 32 + lrow;
        bbase0 = OFF_BT + rowb * 128 + ((lch ^ (rowb & 7)) * 16);
    }

    float Cr[4][4][4];
#pragma unroll
    for (int mt = 0; mt < 4; mt++)
#pragma unroll
        for (int nt = 0; nt < 4; nt++)
#pragma unroll
            for (int j = 0; j < 4; j++) Cr[mt][nt][j] = 0.f;

#pragma unroll
    for (int c = 0; c < 2; c++) {
        const int k0 = c * 64;
        const unsigned stg = sbase + c * STAGE;
#pragma unroll
        for (int i = 0; i < 4; i++)
            cpa16(stg + a_dst0 + i * 4096, g_fhi + k0 + a_src0 + i * 16384);
#pragma unroll
        for (int i = 0; i < 4; i++)
            cpa16(stg + b_dst0 + i * 4096, g_w1t + k0 + b_src0 + i * 16384);
        cpa_commit();
    }

    for (int c = 0; c < 8; c++) {
        asm volatile("cp.async.wait_group 1;" ::: "memory");
        __syncthreads();
        if (c + 2 < 8) {
            const int k0 = (c + 2) * 64;
            const unsigned stg = sbase + ((c + 2) % 3) * STAGE;
#pragma unroll
            for (int i = 0; i < 4; i++)
                cpa16(stg + a_dst0 + i * 4096, g_fhi + k0 + a_src0 + i * 16384);
#pragma unroll
            for (int i = 0; i < 4; i++)
                cpa16(stg + b_dst0 + i * 4096, g_w1t + k0 + b_src0 + i * 16384);
        }
        cpa_commit();

        const unsigned Ab = sbase + (c % 3) * STAGE;
#pragma unroll
        for (int kk = 0; kk < 4; kk++) {
            const unsigned kx = kk << 5;
            unsigned bf[4][2];
#pragma unroll
            for (int np = 0; np < 2; np++) {
                unsigned t0, t1, t2, t3;
                ldsm4(Ab + ((bbase0 + np * 2048) ^ kx), t0, t1, t2, t3);
                bf[np * 2][0] = t0; bf[np * 2][1] = t2;
                bf[np * 2 + 1][0] = t1; bf[np * 2 + 1][1] = t3;
            }
            unsigned ah[4][4];
#pragma unroll
            for (int mt = 0; mt < 4; mt++)
                ldsm4(Ab + ((abase0 + mt * 2048) ^ kx),
                      ah[mt][0], ah[mt][1], ah[mt][2], ah[mt][3]);
#pragma unroll
            for (int mt = 0; mt < 4; mt++)
#pragma unroll
                for (int nt = 0; nt < 4; nt++)
                    mma16816(Cr[mt][nt], ah[mt][0], ah[mt][1], ah[mt][2], ah[mt][3],
                             bf[nt][0], bf[nt][1]);
        }
    }

    float p0[4], p1[4];
#pragma unroll
    for (int mt = 0; mt < 4; mt++) { p0[mt] = 0.f; p1[mt] = 0.f; }
#pragma unroll
    for (int mt = 0; mt < 4; mt++)
#pragma unroll
        for (int nt = 0; nt < 4; nt++) {
            int nc = wn * 32 + nt * 8 + (lid & 3) * 2;
            float ph0 = shPh[nc], ph1 = shPh[nc + 1];
            float v0 = shV[nc], v1 = shV[nc + 1];
            p0[mt] += ftanh(Cr[mt][nt][0] + ph0) * v0
                    + ftanh(Cr[mt][nt][1] + ph1) * v1;
            p1[mt] += ftanh(Cr[mt][nt][2] + ph0) * v0
                    + ftanh(Cr[mt][nt][3] + ph1) * v1;
        }
#pragma unroll
    for (int mt = 0; mt < 4; mt++) {
        p0[mt] += __shfl_xor_sync(0xFFFFFFFFu, p0[mt], 1);
        p0[mt] += __shfl_xor_sync(0xFFFFFFFFu, p0[mt], 2);
        p1[mt] += __shfl_xor_sync(0xFFFFFFFFu, p1[mt], 1);
        p1[mt] += __shfl_xor_sync(0xFFFFFFFFu, p1[mt], 2);
    }
    if ((lid & 3) == 0) {
#pragma unroll
        for (int mt = 0; mt < 4; mt++) {
            int rl = wm * 64 + mt * 16 + (lid >> 2);
            red[rl][wn] = p0[mt];
            red[rl + 8][wn] = p1[mt];
        }
    }
    __syncthreads();
    if (tid < 128) {
        float s = red[tid][0] + red[tid][1] + red[tid][2] + red[tid][3];
        g_lpart[nq][bt0 + tid] = s;
    }
}

// ---------------------------------------------------------------------------
// softmax over T: grid B_, 256 threads; writes weights to g_ws + output
// ---------------------------------------------------------------------------
__global__ void softmax_w_kernel(const float* __restrict__ Vb,
                                 float* __restrict__ out) {
    __shared__ float rbuf[8];
    const int b = blockIdx.x;
    const int tid = threadIdx.x;
    const int wid = tid >> 5, lid = tid & 31;
    const float vb = Vb[0];

    float l[4];
    float mx = -1e30f;
#pragma unroll
    for (int i = 0; i < 4; i++) {
        int idx = b * T_ + tid * 4 + i;
        float s = vb;
#pragma unroll
        for (int q = 0; q < 8; q++) s += g_lpart[q][idx];
        l[i] = s;
        mx = fmaxf(mx, l[i]);
    }
#pragma unroll
    for (int s = 16; s > 0; s >>= 1) mx = fmaxf(mx, __shfl_xor_sync(~0u, mx, s));
    if (lid == 0) rbuf[wid] = mx;
    __syncthreads();
    float m8 = rbuf[lid & 7];
#pragma unroll
    for (int s = 4; s > 0; s >>= 1) m8 = fmaxf(m8, __shfl_xor_sync(~0u, m8, s));
    mx = __shfl_sync(~0u, m8, 0);

    float ssum = 0.f;
#pragma unroll
    for (int i = 0; i < 4; i++) {
        l[i] = expf(l[i] - mx);
        ssum += l[i];
    }
#pragma unroll
    for (int s = 16; s > 0; s >>= 1) ssum += __shfl_xor_sync(~0u, ssum, s);
    __syncthreads();
    if (lid == 0) rbuf[wid] = ssum;
    __syncthreads();
    float s8 = rbuf[lid & 7];
#pragma unroll
    for (int s = 4; s > 0; s >>= 1) s8 += __shfl_xor_sync(~0u, s8, s);
    const float inv = 1.0f / __shfl_sync(~0u, s8, 0);

    float4 w4 = make_float4(l[0] * inv, l[1] * inv, l[2] * inv, l[3] * inv);
    ((float4*)(g_ws + b * T_))[tid] = w4;
    ((float4*)(out + B_ * D_ + b * T_))[tid] = w4;
}

// ---------------------------------------------------------------------------
// context vector: grid (B_, D/128), 512 threads = 16 T-splits x 32 d-quads
// uint2 loads (4 halves = 8B/thread, 256B/warp) for 4x MLP bytes
// ---------------------------------------------------------------------------
__global__ void __launch_bounds__(512)
ctx_kernel(float* __restrict__ out) {
    __shared__ float ws[T_];
    __shared__ float red[16][128];
    const int b = blockIdx.x;
    const int d0 = blockIdx.y * 128;
    const int tid = threadIdx.x;
    const int dl = tid & 31;     // d-quad index (4 d-lanes each)
    const int tq = tid >> 5;     // 16 T-splits of 64

    ((float2*)ws)[tid] = ((const float2*)(g_ws + b * T_))[tid];
    __syncthreads();

    const __half* fb = g_fhi + (size_t)b * T_ * D_ + (size_t)tq * 64 * D_ + d0 + dl * 4;
    const float* wq = ws + tq * 64;
    float4 acc = make_float4(0.f, 0.f, 0.f, 0.f);
#pragma unroll 8
    for (int t = 0; t < 64; t++) {
        float w = wq[t];
        uint2 h = *(const uint2*)(fb + (size_t)t * D_);
        float2 f0 = __half22float2(*(const __half2*)&h.x);
        float2 f1 = __half22float2(*(const __half2*)&h.y);
        acc.x += w * f0.x; acc.y += w * f0.y;
        acc.z += w * f1.x; acc.w += w * f1.y;
    }
    red[tq][dl * 4 + 0] = acc.x;
    red[tq][dl * 4 + 1] = acc.y;
    red[tq][dl * 4 + 2] = acc.z;
    red[tq][dl * 4 + 3] = acc.w;
    __syncthreads();
    if (tid < 128) {
        float s = 0.f;
#pragma unroll
        for (int q = 0; q < 16; q++) s += red[q][tid];
        out[b * D_ + d0 + tid] = s;
    }
}

// ---------------------------------------------------------------------------
extern "C" void kernel_launch(void* const* d_in, const int* in_sizes, int n_in,
                              void* d_out, int out_size) {
    const float* feat   = (const float*)d_in[0];
    const float* hidden = (const float*)d_in[1];
    const float* W1w    = (const float*)d_in[2];
    const float* W1b    = (const float*)d_in[3];
    const float* W2w    = (const float*)d_in[4];
    const float* W2b    = (const float*)d_in[5];
    const float* Vw     = (const float*)d_in[6];
    const float* Vb     = (const float*)d_in[7];
    float* out = (float*)d_out;

    static bool attr_set = false;
    if (!attr_set) {
        cudaFuncSetAttribute(score_kernel, cudaFuncAttributeMaxDynamicSharedMemorySize,
                             SMEM_TOTAL);
        attr_set = true;
    }

    prep_kernel<<<NF_BLK + NW_BLK + NP_BLK, 256>>>(feat, W1w, hidden, W2w, W2b);
    score_kernel<<<dim3(8, BT / 128), 256, SMEM_TOTAL>>>(W1b, Vw);
    softmax_w_kernel<<<B_, 256>>>(Vb, out);
    ctx_kernel<<<dim3(B_, D_ / 128), 512>>>(out);
}

// round 14
// speedup vs baseline: 1.1369x; 1.0253x over previous
#include <cuda_runtime.h>
#include <cuda_fp16.h>
#include <math.h>

#define B_ 64
#define T_ 1024
#define D_ 512
#define U_ 1024
#define BT (B_ * T_)

// ---------------- device scratch (no allocation allowed) ----------------
__device__ __align__(128) __half g_fhi[BT * D_];   // 64 MB
__device__ __align__(128) __half g_w1t[U_ * D_];   // [n][k], 1 MB
__device__ float g_projh[B_ * U_];
__device__ float g_lpart[8][BT];   // per-n-eighth logit partials

// ---------------- PTX helpers ----------------
__device__ __forceinline__ unsigned smem_u32(const void* p) {
    unsigned a;
    asm("{ .reg .u64 t; cvta.to.shared.u64 t, %1; cvt.u32.u64 %0, t; }"
        : "=r"(a) : "l"(p));
    return a;
}
__device__ __forceinline__ void cpa16(unsigned dst, const void* src) {
    asm volatile("cp.async.cg.shared.global [%0], [%1], 16;" :: "r"(dst), "l"(src));
}
__device__ __forceinline__ void cpa_commit() { asm volatile("cp.async.commit_group;"); }
__device__ __forceinline__ void ldsm4(unsigned addr, unsigned& r0, unsigned& r1,
                                      unsigned& r2, unsigned& r3) {
    asm volatile("ldmatrix.sync.aligned.m8n8.x4.shared.b16 {%0,%1,%2,%3}, [%4];"
                 : "=r"(r0), "=r"(r1), "=r"(r2), "=r"(r3) : "r"(addr));
}
__device__ __forceinline__ void mma16816(float* c, unsigned a0, unsigned a1,
                                         unsigned a2, unsigned a3,
                                         unsigned b0, unsigned b1) {
    asm volatile(
        "mma.sync.aligned.m16n8k16.row.col.f32.f16.f16.f32 "
        "{%0,%1,%2,%3}, {%4,%5,%6,%7}, {%8,%9}, {%0,%1,%2,%3};"
        : "+f"(c[0]), "+f"(c[1]), "+f"(c[2]), "+f"(c[3])
        : "r"(a0), "r"(a1), "r"(a2), "r"(a3), "r"(b0), "r"(b1));
}
// fast tanh: 1 - 2/(e^{2x}+1). abs err ~2e-7.
__device__ __forceinline__ float ftanh(float x) {
    float e = __expf(2.0f * x);
    return 1.0f - __fdividef(2.0f, e + 1.0f);
}

// ---------------- smem layout for score kernel (2 CTAs/SM) ----------------
#define STAGE 32768            // A (128x64 fp16 = 16KB) + B (128x64 fp16 = 16KB)
#define OFF_BT 16384
#define OFF_PH 98304           // 128 floats
#define OFF_V  98816           // 128 floats
#define OFF_RED 99328          // 128 x 4 floats
#define SMEM_TOTAL 101376

// ---------------------------------------------------------------------------
// prep kernel: fused  fsplit (fp32->fp16 feat) + W1 transpose + proj_h GEMV
// ---------------------------------------------------------------------------
#define NF_BLK (BT * D_ / 4 / 256)   // 32768
#define NW_BLK 512                   // (U/32) x (D/32)
#define NP_BLK 32                    // (U/256) x (B/8)
__global__ void __launch_bounds__(256)
prep_kernel(const float* __restrict__ feat, const float* __restrict__ W1,
            const float* __restrict__ hidden, const float* __restrict__ W2,
            const float* __restrict__ W2b) {
    __shared__ __align__(16) char sbuf[16384];
    const int bid = blockIdx.x;
    const int tid = threadIdx.x;

    if (bid < NF_BLK) {
        long i = (long)bid * 256 + tid;
        float4 v = ((const float4*)feat)[i];
        uint2 hw;
        hw.x = (unsigned)__half_as_ushort(__float2half_rn(v.x)) |
               ((unsigned)__half_as_ushort(__float2half_rn(v.y)) << 16);
        hw.y = (unsigned)__half_as_ushort(__float2half_rn(v.z)) |
               ((unsigned)__half_as_ushort(__float2half_rn(v.w)) << 16);
        ((uint2*)g_fhi)[i] = hw;
    } else if (bid < NF_BLK + NW_BLK) {
        float (*tile)[33] = (float(*)[33])sbuf;
        const int wb = bid - NF_BLK;
        const int n0 = (wb & 31) * 32, k0 = (wb >> 5) * 32;
        const int tx = tid & 31, ty = tid >> 5;
        for (int r = ty; r < 32; r += 8)
            tile[r][tx] = W1[(size_t)(k0 + r) * U_ + n0 + tx];
        __syncthreads();
        for (int rr = ty; rr < 32; rr += 8)
            g_w1t[(size_t)(n0 + rr) * D_ + k0 + tx] = __float2half_rn(tile[tx][rr]);
    } else {
        float (*hs)[D_] = (float(*)[D_])sbuf;
        const int pb = bid - NF_BLK - NW_BLK;
        const int u = (pb & 3) * 256 + tid;
        const int b0 = (pb >> 2) * 8;
#pragma unroll
        for (int i = 0; i < 4; i++)
            ((float4*)hs)[tid + i * 256] =
                ((const float4*)(hidden + (size_t)b0 * D_))[tid + i * 256];
        __syncthreads();
        float acc[8];
#pragma unroll
        for (int i = 0; i < 8; i++) acc[i] = 0.f;
#pragma unroll 4
        for (int k = 0; k < D_; k++) {
            float w = W2[(size_t)k * U_ + u];
#pragma unroll
            for (int bb = 0; bb < 8; bb++) acc[bb] += hs[bb][k] * w;
        }
        float bias = W2b[u];
#pragma unroll
        for (int bb = 0; bb < 8; bb++)
            g_projh[(size_t)(b0 + bb) * U_ + u] = acc[bb] + bias;
    }
}

// ---------------------------------------------------------------------------
// score kernel: fp16 mma.sync GEMM + fast-tanh + V-dot epilogue
// (unchanged from R12 — 2 CTAs/SM win)
// ---------------------------------------------------------------------------
__global__ void __launch_bounds__(256, 2)
score_kernel(const float* __restrict__ W1b, const float* __restrict__ Vw) {
    extern __shared__ __align__(1024) char smem[];
    const unsigned sbase = smem_u32(smem);
    const int tid = threadIdx.x;
    const int wid = tid >> 5, lid = tid & 31;
    const int wm = wid & 1, wn = wid >> 1;       // 2 x 4 warp grid, tile 64m x 32n
    const int nq = blockIdx.x;
    const int bt0 = blockIdx.y * 128;
    const int b = bt0 >> 10;
    const int n0 = nq * 128;
    float* shPh = (float*)(smem + OFF_PH);
    float* shV  = (float*)(smem + OFF_V);
    float (*red)[4] = (float(*)[4])(smem + OFF_RED);

    if (tid < 128) {
        shPh[tid] = g_projh[(size_t)b * U_ + n0 + tid] + W1b[n0 + tid];
        shV[tid]  = Vw[n0 + tid];
    }

    unsigned a_src0, a_dst0, b_src0, b_dst0;
    {
        int row = tid >> 3, c16 = tid & 7;
        a_src0 = (unsigned)((bt0 + row) * D_ + c16 * 8);
        a_dst0 = row * 128 + ((c16 ^ (row & 7)) * 16);
        b_src0 = (unsigned)((n0 + row) * D_ + c16 * 8);
        b_dst0 = OFF_BT + row * 128 + ((c16 ^ (row & 7)) * 16);
    }

    const int lrow = lid & 15;
    const int lch  = lid >> 4;
    unsigned abase0, bbase0;
    {
        int row = wm * 64 + lrow;
        abase0 = row * 128 + ((lch ^ (row & 7)) * 16);
        int rowb = wn * 32 + lrow;
        bbase0 = OFF_BT + rowb * 128 + ((lch ^ (rowb & 7)) * 16);
    }

    float Cr[4][4][4];
#pragma unroll
    for (int mt = 0; mt < 4; mt++)
#pragma unroll
        for (int nt = 0; nt < 4; nt++)
#pragma unroll
            for (int j = 0; j < 4; j++) Cr[mt][nt][j] = 0.f;

#pragma unroll
    for (int c = 0; c < 2; c++) {
        const int k0 = c * 64;
        const unsigned stg = sbase + c * STAGE;
#pragma unroll
        for (int i = 0; i < 4; i++)
            cpa16(stg + a_dst0 + i * 4096, g_fhi + k0 + a_src0 + i * 16384);
#pragma unroll
        for (int i = 0; i < 4; i++)
            cpa16(stg + b_dst0 + i * 4096, g_w1t + k0 + b_src0 + i * 16384);
        cpa_commit();
    }

    for (int c = 0; c < 8; c++) {
        asm volatile("cp.async.wait_group 1;" ::: "memory");
        __syncthreads();
        if (c + 2 < 8) {
            const int k0 = (c + 2) * 64;
            const unsigned stg = sbase + ((c + 2) % 3) * STAGE;
#pragma unroll
            for (int i = 0; i < 4; i++)
                cpa16(stg + a_dst0 + i * 4096, g_fhi + k0 + a_src0 + i * 16384);
#pragma unroll
            for (int i = 0; i < 4; i++)
                cpa16(stg + b_dst0 + i * 4096, g_w1t + k0 + b_src0 + i * 16384);
        }
        cpa_commit();

        const unsigned Ab = sbase + (c % 3) * STAGE;
#pragma unroll
        for (int kk = 0; kk < 4; kk++) {
            const unsigned kx = kk << 5;
            unsigned bf[4][2];
#pragma unroll
            for (int np = 0; np < 2; np++) {
                unsigned t0, t1, t2, t3;
                ldsm4(Ab + ((bbase0 + np * 2048) ^ kx), t0, t1, t2, t3);
                bf[np * 2][0] = t0; bf[np * 2][1] = t2;
                bf[np * 2 + 1][0] = t1; bf[np * 2 + 1][1] = t3;
            }
            unsigned ah[4][4];
#pragma unroll
            for (int mt = 0; mt < 4; mt++)
                ldsm4(Ab + ((abase0 + mt * 2048) ^ kx),
                      ah[mt][0], ah[mt][1], ah[mt][2], ah[mt][3]);
#pragma unroll
            for (int mt = 0; mt < 4; mt++)
#pragma unroll
                for (int nt = 0; nt < 4; nt++)
                    mma16816(Cr[mt][nt], ah[mt][0], ah[mt][1], ah[mt][2], ah[mt][3],
                             bf[nt][0], bf[nt][1]);
        }
    }

    float p0[4], p1[4];
#pragma unroll
    for (int mt = 0; mt < 4; mt++) { p0[mt] = 0.f; p1[mt] = 0.f; }
#pragma unroll
    for (int mt = 0; mt < 4; mt++)
#pragma unroll
        for (int nt = 0; nt < 4; nt++) {
            int nc = wn * 32 + nt * 8 + (lid & 3) * 2;
            float ph0 = shPh[nc], ph1 = shPh[nc + 1];
            float v0 = shV[nc], v1 = shV[nc + 1];
            p0[mt] += ftanh(Cr[mt][nt][0] + ph0) * v0
                    + ftanh(Cr[mt][nt][1] + ph1) * v1;
            p1[mt] += ftanh(Cr[mt][nt][2] + ph0) * v0
                    + ftanh(Cr[mt][nt][3] + ph1) * v1;
        }
#pragma unroll
    for (int mt = 0; mt < 4; mt++) {
        p0[mt] += __shfl_xor_sync(0xFFFFFFFFu, p0[mt], 1);
        p0[mt] += __shfl_xor_sync(0xFFFFFFFFu, p0[mt], 2);
        p1[mt] += __shfl_xor_sync(0xFFFFFFFFu, p1[mt], 1);
        p1[mt] += __shfl_xor_sync(0xFFFFFFFFu, p1[mt], 2);
    }
    if ((lid & 3) == 0) {
#pragma unroll
        for (int mt = 0; mt < 4; mt++) {
            int rl = wm * 64 + mt * 16 + (lid >> 2);
            red[rl][wn] = p0[mt];
            red[rl + 8][wn] = p1[mt];
        }
    }
    __syncthreads();
    if (tid < 128) {
        float s = red[tid][0] + red[tid][1] + red[tid][2] + red[tid][3];
        g_lpart[nq][bt0 + tid] = s;
    }
}

// ---------------------------------------------------------------------------
// fused softmax + context kernel: grid (B_, D/128), 1024 threads
// phase 1: softmax over T from g_lpart (recomputed per d-split; 32KB reads)
// phase 2: context = 32 T-splits x 32 d-quads, uint2 fp16 loads
// ---------------------------------------------------------------------------
__global__ void __launch_bounds__(1024)
softctx_kernel(const float* __restrict__ Vb, float* __restrict__ out) {
    __shared__ float ws[T_];
    __shared__ float rbuf[32];
    __shared__ float red[32][128];
    const int b = blockIdx.x;
    const int d0 = blockIdx.y * 128;
    const int tid = threadIdx.x;
    const int wid = tid >> 5, lid = tid & 31;

    // ---- softmax over T (each thread owns one logit) ----
    float l = Vb[0];
    {
        const int idx = b * T_ + tid;
#pragma unroll
        for (int q = 0; q < 8; q++) l += g_lpart[q][idx];
    }
    float mx = l;
#pragma unroll
    for (int s = 16; s > 0; s >>= 1) mx = fmaxf(mx, __shfl_xor_sync(~0u, mx, s));
    if (lid == 0) rbuf[wid] = mx;
    __syncthreads();
    if (tid < 32) {
        float m = rbuf[tid];
#pragma unroll
        for (int s = 16; s > 0; s >>= 1) m = fmaxf(m, __shfl_xor_sync(~0u, m, s));
        rbuf[tid] = m;   // all 32 lanes hold the max
    }
    __syncthreads();
    mx = rbuf[0];
    float e = __expf(l - mx);
    float ssum = e;
#pragma unroll
    for (int s = 16; s > 0; s >>= 1) ssum += __shfl_xor_sync(~0u, ssum, s);
    __syncthreads();   // rbuf reads above done before rewrite
    if (lid == 0) rbuf[wid] = ssum;
    __syncthreads();
    if (tid < 32) {
        float m = rbuf[tid];
#pragma unroll
        for (int s = 16; s > 0; s >>= 1) m += __shfl_xor_sync(~0u, m, s);
        rbuf[tid] = m;
    }
    __syncthreads();
    const float w = e * __fdividef(1.0f, rbuf[0]);
    ws[tid] = w;
    if (blockIdx.y == 0) out[B_ * D_ + b * T_ + tid] = w;   // attention weights
    __syncthreads();

    // ---- context: 32 T-splits x 32 d-quads ----
    const int dl = tid & 31;     // d-quad (4 d each)
    const int tq = tid >> 5;     // 32 T-splits of 32
    const __half* fb = g_fhi + (size_t)b * T_ * D_ + (size_t)tq * 32 * D_ + d0 + dl * 4;
    const float* wq = ws + tq * 32;
    float4 acc = make_float4(0.f, 0.f, 0.f, 0.f);
#pragma unroll 8
    for (int t = 0; t < 32; t++) {
        float wv = wq[t];
        uint2 h = *(const uint2*)(fb + (size_t)t * D_);
        float2 f0 = __half22float2(*(const __half2*)&h.x);
        float2 f1 = __half22float2(*(const __half2*)&h.y);
        acc.x += wv * f0.x; acc.y += wv * f0.y;
        acc.z += wv * f1.x; acc.w += wv * f1.y;
    }
    red[tq][dl * 4 + 0] = acc.x;
    red[tq][dl * 4 + 1] = acc.y;
    red[tq][dl * 4 + 2] = acc.z;
    red[tq][dl * 4 + 3] = acc.w;
    __syncthreads();
    if (tid < 128) {
        float s = 0.f;
#pragma unroll
        for (int q = 0; q < 32; q++) s += red[q][tid];
        out[b * D_ + d0 + tid] = s;
    }
}

// ---------------------------------------------------------------------------
extern "C" void kernel_launch(void* const* d_in, const int* in_sizes, int n_in,
                              void* d_out, int out_size) {
    const float* feat   = (const float*)d_in[0];
    const float* hidden = (const float*)d_in[1];
    const float* W1w    = (const float*)d_in[2];
    const float* W1b    = (const float*)d_in[3];
    const float* W2w    = (const float*)d_in[4];
    const float* W2b    = (const float*)d_in[5];
    const float* Vw     = (const float*)d_in[6];
    const float* Vb     = (const float*)d_in[7];
    float* out = (float*)d_out;

    static bool attr_set = false;
    if (!attr_set) {
        cudaFuncSetAttribute(score_kernel, cudaFuncAttributeMaxDynamicSharedMemorySize,
                             SMEM_TOTAL);
        attr_set = true;
    }

    prep_kernel<<<NF_BLK + NW_BLK + NP_BLK, 256>>>(feat, W1w, hidden, W2w, W2b);
    score_kernel<<<dim3(8, BT / 128), 256, SMEM_TOTAL>>>(W1b, Vw);
    softctx_kernel<<<dim3(B_, D_ / 128), 1024>>>(Vb, out);
}

// round 15
// speedup vs baseline: 1.1852x; 1.0425x over previous
#include <cuda_runtime.h>
#include <cuda_fp16.h>
#include <math.h>

#define B_ 64
#define T_ 1024
#define D_ 512
#define U_ 1024
#define BT (B_ * T_)

// ---------------- device scratch (no allocation allowed) ----------------
__device__ __align__(128) __half g_fhi[BT * D_];   // 64 MB
__device__ __align__(128) __half g_w1t[U_ * D_];   // [n][k], 1 MB
__device__ float g_projh[B_ * U_];
__device__ float g_lpart[8][BT];   // per-n-eighth logit partials

// ---------------- PTX helpers ----------------
__device__ __forceinline__ unsigned smem_u32(const void* p) {
    unsigned a;
    asm("{ .reg .u64 t; cvta.to.shared.u64 t, %1; cvt.u32.u64 %0, t; }"
        : "=r"(a) : "l"(p));
    return a;
}
__device__ __forceinline__ void cpa16(unsigned dst, const void* src) {
    asm volatile("cp.async.cg.shared.global [%0], [%1], 16;" :: "r"(dst), "l"(src));
}
__device__ __forceinline__ void cpa_commit() { asm volatile("cp.async.commit_group;"); }
__device__ __forceinline__ void ldsm4(unsigned addr, unsigned& r0, unsigned& r1,
                                      unsigned& r2, unsigned& r3) {
    asm volatile("ldmatrix.sync.aligned.m8n8.x4.shared.b16 {%0,%1,%2,%3}, [%4];"
                 : "=r"(r0), "=r"(r1), "=r"(r2), "=r"(r3) : "r"(addr));
}
__device__ __forceinline__ void mma16816(float* c, unsigned a0, unsigned a1,
                                         unsigned a2, unsigned a3,
                                         unsigned b0, unsigned b1) {
    asm volatile(
        "mma.sync.aligned.m16n8k16.row.col.f32.f16.f16.f32 "
        "{%0,%1,%2,%3}, {%4,%5,%6,%7}, {%8,%9}, {%0,%1,%2,%3};"
        : "+f"(c[0]), "+f"(c[1]), "+f"(c[2]), "+f"(c[3])
        : "r"(a0), "r"(a1), "r"(a2), "r"(a3), "r"(b0), "r"(b1));
}
// fast tanh: 1 - 2/(e^{2x}+1). abs err ~2e-7.
__device__ __forceinline__ float ftanh(float x) {
    float e = __expf(2.0f * x);
    return 1.0f - __fdividef(2.0f, e + 1.0f);
}

// ---------------- smem layout for score kernel (2 CTAs/SM) ----------------
#define STAGE 32768            // A (128x64 fp16 = 16KB) + B (128x64 fp16 = 16KB)
#define OFF_BT 16384
#define OFF_PH 98304           // 128 floats
#define OFF_V  98816           // 128 floats
#define OFF_RED 99328          // 128 x 4 floats
#define SMEM_TOTAL 101376

// ---------------------------------------------------------------------------
// prep kernel: fused  fsplit (fp32->fp16, 4 float4/thread for MLP=4)
//              + W1 transpose + proj_h GEMV
// ---------------------------------------------------------------------------
#define NF_BLK (BT * D_ / 16 / 256)  // 8192 (each thread: 4 float4)
#define NW_BLK 512                   // (U/32) x (D/32)
#define NP_BLK 32                    // (U/256) x (B/8)
__global__ void __launch_bounds__(256)
prep_kernel(const float* __restrict__ feat, const float* __restrict__ W1,
            const float* __restrict__ hidden, const float* __restrict__ W2,
            const float* __restrict__ W2b) {
    __shared__ __align__(16) char sbuf[16384];
    const int bid = blockIdx.x;
    const int tid = threadIdx.x;

    if (bid < NF_BLK) {
        // ---- feat fp32 -> fp16, 4 independent float4 loads per thread ----
        const long base = (long)bid * 1024 + tid;
        float4 v[4];
#pragma unroll
        for (int j = 0; j < 4; j++)
            v[j] = ((const float4*)feat)[base + j * 256];
#pragma unroll
        for (int j = 0; j < 4; j++) {
            uint2 hw;
            hw.x = (unsigned)__half_as_ushort(__float2half_rn(v[j].x)) |
                   ((unsigned)__half_as_ushort(__float2half_rn(v[j].y)) << 16);
            hw.y = (unsigned)__half_as_ushort(__float2half_rn(v[j].z)) |
                   ((unsigned)__half_as_ushort(__float2half_rn(v[j].w)) << 16);
            ((uint2*)g_fhi)[base + j * 256] = hw;
        }
    } else if (bid < NF_BLK + NW_BLK) {
        float (*tile)[33] = (float(*)[33])sbuf;
        const int wb = bid - NF_BLK;
        const int n0 = (wb & 31) * 32, k0 = (wb >> 5) * 32;
        const int tx = tid & 31, ty = tid >> 5;
        for (int r = ty; r < 32; r += 8)
            tile[r][tx] = W1[(size_t)(k0 + r) * U_ + n0 + tx];
        __syncthreads();
        for (int rr = ty; rr < 32; rr += 8)
            g_w1t[(size_t)(n0 + rr) * D_ + k0 + tx] = __float2half_rn(tile[tx][rr]);
    } else {
        float (*hs)[D_] = (float(*)[D_])sbuf;
        const int pb = bid - NF_BLK - NW_BLK;
        const int u = (pb & 3) * 256 + tid;
        const int b0 = (pb >> 2) * 8;
#pragma unroll
        for (int i = 0; i < 4; i++)
            ((float4*)hs)[tid + i * 256] =
                ((const float4*)(hidden + (size_t)b0 * D_))[tid + i * 256];
        __syncthreads();
        float acc[8];
#pragma unroll
        for (int i = 0; i < 8; i++) acc[i] = 0.f;
#pragma unroll 4
        for (int k = 0; k < D_; k++) {
            float w = W2[(size_t)k * U_ + u];
#pragma unroll
            for (int bb = 0; bb < 8; bb++) acc[bb] += hs[bb][k] * w;
        }
        float bias = W2b[u];
#pragma unroll
        for (int bb = 0; bb < 8; bb++)
            g_projh[(size_t)(b0 + bb) * U_ + u] = acc[bb] + bias;
    }
}

// ---------------------------------------------------------------------------
// score kernel: fp16 mma.sync GEMM + fast-tanh + V-dot epilogue
// (unchanged from R12 — 2 CTAs/SM win)
// ---------------------------------------------------------------------------
__global__ void __launch_bounds__(256, 2)
score_kernel(const float* __restrict__ W1b, const float* __restrict__ Vw) {
    extern __shared__ __align__(1024) char smem[];
    const unsigned sbase = smem_u32(smem);
    const int tid = threadIdx.x;
    const int wid = tid >> 5, lid = tid & 31;
    const int wm = wid & 1, wn = wid >> 1;       // 2 x 4 warp grid, tile 64m x 32n
    const int nq = blockIdx.x;
    const int bt0 = blockIdx.y * 128;
    const int b = bt0 >> 10;
    const int n0 = nq * 128;
    float* shPh = (float*)(smem + OFF_PH);
    float* shV  = (float*)(smem + OFF_V);
    float (*red)[4] = (float(*)[4])(smem + OFF_RED);

    if (tid < 128) {
        shPh[tid] = g_projh[(size_t)b * U_ + n0 + tid] + W1b[n0 + tid];
        shV[tid]  = Vw[n0 + tid];
    }

    unsigned a_src0, a_dst0, b_src0, b_dst0;
    {
        int row = tid >> 3, c16 = tid & 7;
        a_src0 = (unsigned)((bt0 + row) * D_ + c16 * 8);
        a_dst0 = row * 128 + ((c16 ^ (row & 7)) * 16);
        b_src0 = (unsigned)((n0 + row) * D_ + c16 * 8);
        b_dst0 = OFF_BT + row * 128 + ((c16 ^ (row & 7)) * 16);
    }

    const int lrow = lid & 15;
    const int lch  = lid >> 4;
    unsigned abase0, bbase0;
    {
        int row = wm * 64 + lrow;
        abase0 = row * 128 + ((lch ^ (row & 7)) * 16);
        int rowb = wn * 32 + lrow;
        bbase0 = OFF_BT + rowb * 128 + ((lch ^ (rowb & 7)) * 16);
    }

    float Cr[4][4][4];
#pragma unroll
    for (int mt = 0; mt < 4; mt++)
#pragma unroll
        for (int nt = 0; nt < 4; nt++)
#pragma unroll
            for (int j = 0; j < 4; j++) Cr[mt][nt][j] = 0.f;

#pragma unroll
    for (int c = 0; c < 2; c++) {
        const int k0 = c * 64;
        const unsigned stg = sbase + c * STAGE;
#pragma unroll
        for (int i = 0; i < 4; i++)
            cpa16(stg + a_dst0 + i * 4096, g_fhi + k0 + a_src0 + i * 16384);
#pragma unroll
        for (int i = 0; i < 4; i++)
            cpa16(stg + b_dst0 + i * 4096, g_w1t + k0 + b_src0 + i * 16384);
        cpa_commit();
    }

    for (int c = 0; c < 8; c++) {
        asm volatile("cp.async.wait_group 1;" ::: "memory");
        __syncthreads();
        if (c + 2 < 8) {
            const int k0 = (c + 2) * 64;
            const unsigned stg = sbase + ((c + 2) % 3) * STAGE;
#pragma unroll
            for (int i = 0; i < 4; i++)
                cpa16(stg + a_dst0 + i * 4096, g_fhi + k0 + a_src0 + i * 16384);
#pragma unroll
            for (int i = 0; i < 4; i++)
                cpa16(stg + b_dst0 + i * 4096, g_w1t + k0 + b_src0 + i * 16384);
        }
        cpa_commit();

        const unsigned Ab = sbase + (c % 3) * STAGE;
#pragma unroll
        for (int kk = 0; kk < 4; kk++) {
            const unsigned kx = kk << 5;
            unsigned bf[4][2];
#pragma unroll
            for (int np = 0; np < 2; np++) {
                unsigned t0, t1, t2, t3;
                ldsm4(Ab + ((bbase0 + np * 2048) ^ kx), t0, t1, t2, t3);
                bf[np * 2][0] = t0; bf[np * 2][1] = t2;
                bf[np * 2 + 1][0] = t1; bf[np * 2 + 1][1] = t3;
            }
            unsigned ah[4][4];
#pragma unroll
            for (int mt = 0; mt < 4; mt++)
                ldsm4(Ab + ((abase0 + mt * 2048) ^ kx),
                      ah[mt][0], ah[mt][1], ah[mt][2], ah[mt][3]);
#pragma unroll
            for (int mt = 0; mt < 4; mt++)
#pragma unroll
                for (int nt = 0; nt < 4; nt++)
                    mma16816(Cr[mt][nt], ah[mt][0], ah[mt][1], ah[mt][2], ah[mt][3],
                             bf[nt][0], bf[nt][1]);
        }
    }

    float p0[4], p1[4];
#pragma unroll
    for (int mt = 0; mt < 4; mt++) { p0[mt] = 0.f; p1[mt] = 0.f; }
#pragma unroll
    for (int mt = 0; mt < 4; mt++)
#pragma unroll
        for (int nt = 0; nt < 4; nt++) {
            int nc = wn * 32 + nt * 8 + (lid & 3) * 2;
            float ph0 = shPh[nc], ph1 = shPh[nc + 1];
            float v0 = shV[nc], v1 = shV[nc + 1];
            p0[mt] += ftanh(Cr[mt][nt][0] + ph0) * v0
                    + ftanh(Cr[mt][nt][1] + ph1) * v1;
            p1[mt] += ftanh(Cr[mt][nt][2] + ph0) * v0
                    + ftanh(Cr[mt][nt][3] + ph1) * v1;
        }
#pragma unroll
    for (int mt = 0; mt < 4; mt++) {
        p0[mt] += __shfl_xor_sync(0xFFFFFFFFu, p0[mt], 1);
        p0[mt] += __shfl_xor_sync(0xFFFFFFFFu, p0[mt], 2);
        p1[mt] += __shfl_xor_sync(0xFFFFFFFFu, p1[mt], 1);
        p1[mt] += __shfl_xor_sync(0xFFFFFFFFu, p1[mt], 2);
    }
    if ((lid & 3) == 0) {
#pragma unroll
        for (int mt = 0; mt < 4; mt++) {
            int rl = wm * 64 + mt * 16 + (lid >> 2);
            red[rl][wn] = p0[mt];
            red[rl + 8][wn] = p1[mt];
        }
    }
    __syncthreads();
    if (tid < 128) {
        float s = red[tid][0] + red[tid][1] + red[tid][2] + red[tid][3];
        g_lpart[nq][bt0 + tid] = s;
    }
}

// ---------------------------------------------------------------------------
// fused softmax + context kernel: grid (B_, D/128), 1024 threads
// ---------------------------------------------------------------------------
__global__ void __launch_bounds__(1024)
softctx_kernel(const float* __restrict__ Vb, float* __restrict__ out) {
    __shared__ float ws[T_];
    __shared__ float rbuf[32];
    __shared__ float red[32][128];
    const int b = blockIdx.x;
    const int d0 = blockIdx.y * 128;
    const int tid = threadIdx.x;
    const int wid = tid >> 5, lid = tid & 31;

    // ---- softmax over T (each thread owns one logit) ----
    float l = Vb[0];
    {
        const int idx = b * T_ + tid;
#pragma unroll
        for (int q = 0; q < 8; q++) l += g_lpart[q][idx];
    }
    float mx = l;
#pragma unroll
    for (int s = 16; s > 0; s >>= 1) mx = fmaxf(mx, __shfl_xor_sync(~0u, mx, s));
    if (lid == 0) rbuf[wid] = mx;
    __syncthreads();
    if (tid < 32) {
        float m = rbuf[tid];
#pragma unroll
        for (int s = 16; s > 0; s >>= 1) m = fmaxf(m, __shfl_xor_sync(~0u, m, s));
        rbuf[tid] = m;
    }
    __syncthreads();
    mx = rbuf[0];
    float e = __expf(l - mx);
    float ssum = e;
#pragma unroll
    for (int s = 16; s > 0; s >>= 1) ssum += __shfl_xor_sync(~0u, ssum, s);
    __syncthreads();
    if (lid == 0) rbuf[wid] = ssum;
    __syncthreads();
    if (tid < 32) {
        float m = rbuf[tid];
#pragma unroll
        for (int s = 16; s > 0; s >>= 1) m += __shfl_xor_sync(~0u, m, s);
        rbuf[tid] = m;
    }
    __syncthreads();
    const float w = e * __fdividef(1.0f, rbuf[0]);
    ws[tid] = w;
    if (blockIdx.y == 0) out[B_ * D_ + b * T_ + tid] = w;
    __syncthreads();

    // ---- context: 32 T-splits x 32 d-quads ----
    const int dl = tid & 31;
    const int tq = tid >> 5;
    const __half* fb = g_fhi + (size_t)b * T_ * D_ + (size_t)tq * 32 * D_ + d0 + dl * 4;
    const float* wq = ws + tq * 32;
    float4 acc = make_float4(0.f, 0.f, 0.f, 0.f);
#pragma unroll 8
    for (int t = 0; t < 32; t++) {
        float wv = wq[t];
        uint2 h = *(const uint2*)(fb + (size_t)t * D_);
        float2 f0 = __half22float2(*(const __half2*)&h.x);
        float2 f1 = __half22float2(*(const __half2*)&h.y);
        acc.x += wv * f0.x; acc.y += wv * f0.y;
        acc.z += wv * f1.x; acc.w += wv * f1.y;
    }
    red[tq][dl * 4 + 0] = acc.x;
    red[tq][dl * 4 + 1] = acc.y;
    red[tq][dl * 4 + 2] = acc.z;
    red[tq][dl * 4 + 3] = acc.w;
    __syncthreads();
    if (tid < 128) {
        float s = 0.f;
#pragma unroll
        for (int q = 0; q < 32; q++) s += red[q][tid];
        out[b * D_ + d0 + tid] = s;
    }
}

// ---------------------------------------------------------------------------
extern "C" void kernel_launch(void* const* d_in, const int* in_sizes, int n_in,
                              void* d_out, int out_size) {
    const float* feat   = (const float*)d_in[0];
    const float* hidden = (const float*)d_in[1];
    const float* W1w    = (const float*)d_in[2];
    const float* W1b    = (const float*)d_in[3];
    const float* W2w    = (const float*)d_in[4];
    const float* W2b    = (const float*)d_in[5];
    const float* Vw     = (const float*)d_in[6];
    const float* Vb     = (const float*)d_in[7];
    float* out = (float*)d_out;

    static bool attr_set = false;
    if (!attr_set) {
        cudaFuncSetAttribute(score_kernel, cudaFuncAttributeMaxDynamicSharedMemorySize,
                             SMEM_TOTAL);
        attr_set = true;
    }

    prep_kernel<<<NF_BLK + NW_BLK + NP_BLK, 256>>>(feat, W1w, hidden, W2w, W2b);
    score_kernel<<<dim3(8, BT / 128), 256, SMEM_TOTAL>>>(W1b, Vw);
    softctx_kernel<<<dim3(B_, D_ / 128), 1024>>>(Vb, out);
}

// round 16
// speedup vs baseline: 1.2088x; 1.0199x over previous
#include <cuda_runtime.h>
#include <cuda_fp16.h>
#include <math.h>

#define B_ 64
#define T_ 1024
#define D_ 512
#define U_ 1024
#define BT (B_ * T_)

// ---------------- device scratch (no allocation allowed) ----------------
__device__ __align__(128) __half g_fhi[BT * D_];   // 64 MB
__device__ __align__(128) __half g_w1t[U_ * D_];   // [n][k], 1 MB
__device__ float g_projh[B_ * U_];
__device__ float g_lpart[8][BT];   // per-n-eighth logit partials

// ---------------- PTX helpers ----------------
__device__ __forceinline__ unsigned smem_u32(const void* p) {
    unsigned a;
    asm("{ .reg .u64 t; cvta.to.shared.u64 t, %1; cvt.u32.u64 %0, t; }"
        : "=r"(a) : "l"(p));
    return a;
}
__device__ __forceinline__ void cpa16(unsigned dst, const void* src) {
    asm volatile("cp.async.cg.shared.global [%0], [%1], 16;" :: "r"(dst), "l"(src));
}
__device__ __forceinline__ void cpa_commit() { asm volatile("cp.async.commit_group;"); }
__device__ __forceinline__ void ldsm4(unsigned addr, unsigned& r0, unsigned& r1,
                                      unsigned& r2, unsigned& r3) {
    asm volatile("ldmatrix.sync.aligned.m8n8.x4.shared.b16 {%0,%1,%2,%3}, [%4];"
                 : "=r"(r0), "=r"(r1), "=r"(r2), "=r"(r3) : "r"(addr));
}
__device__ __forceinline__ void mma16816(float* c, unsigned a0, unsigned a1,
                                         unsigned a2, unsigned a3,
                                         unsigned b0, unsigned b1) {
    asm volatile(
        "mma.sync.aligned.m16n8k16.row.col.f32.f16.f16.f32 "
        "{%0,%1,%2,%3}, {%4,%5,%6,%7}, {%8,%9}, {%0,%1,%2,%3};"
        : "+f"(c[0]), "+f"(c[1]), "+f"(c[2]), "+f"(c[3])
        : "r"(a0), "r"(a1), "r"(a2), "r"(a3), "r"(b0), "r"(b1));
}
// fast tanh: 1 - 2/(e^{2x}+1). abs err ~2e-7.
__device__ __forceinline__ float ftanh(float x) {
    float e = __expf(2.0f * x);
    return 1.0f - __fdividef(2.0f, e + 1.0f);
}

// ---------------- smem layout for score kernel (2 CTAs/SM) ----------------
#define STAGE 32768            // A (128x64 fp16 = 16KB) + B (128x64 fp16 = 16KB)
#define OFF_BT 16384
#define OFF_PH 98304           // 128 floats
#define OFF_V  98816           // 128 floats
#define OFF_RED 99328          // 128 x 4 floats
#define SMEM_TOTAL 101376

// ---------------------------------------------------------------------------
// prep kernel: fused  fsplit (fp32->fp16, 8 float4/thread MLP, __ldcs)
//              + W1 transpose + proj_h GEMV
// ---------------------------------------------------------------------------
#define NF_BLK (BT * D_ / 32 / 256)  // 4096 (each thread: 8 float4)
#define NW_BLK 512                   // (U/32) x (D/32)
#define NP_BLK 32                    // (U/256) x (B/8)
__global__ void __launch_bounds__(256)
prep_kernel(const float* __restrict__ feat, const float* __restrict__ W1,
            const float* __restrict__ hidden, const float* __restrict__ W2,
            const float* __restrict__ W2b) {
    __shared__ __align__(16) char sbuf[16384];
    const int bid = blockIdx.x;
    const int tid = threadIdx.x;

    if (bid < NF_BLK) {
        // ---- feat fp32 -> fp16, 8 independent streaming float4 loads ----
        const long base = (long)bid * 2048 + tid;
        float4 v[8];
#pragma unroll
        for (int j = 0; j < 8; j++)
            v[j] = __ldcs(((const float4*)feat) + base + j * 256);
#pragma unroll
        for (int j = 0; j < 8; j++) {
            uint2 hw;
            hw.x = (unsigned)__half_as_ushort(__float2half_rn(v[j].x)) |
                   ((unsigned)__half_as_ushort(__float2half_rn(v[j].y)) << 16);
            hw.y = (unsigned)__half_as_ushort(__float2half_rn(v[j].z)) |
                   ((unsigned)__half_as_ushort(__float2half_rn(v[j].w)) << 16);
            ((uint2*)g_fhi)[base + j * 256] = hw;
        }
    } else if (bid < NF_BLK + NW_BLK) {
        float (*tile)[33] = (float(*)[33])sbuf;
        const int wb = bid - NF_BLK;
        const int n0 = (wb & 31) * 32, k0 = (wb >> 5) * 32;
        const int tx = tid & 31, ty = tid >> 5;
        for (int r = ty; r < 32; r += 8)
            tile[r][tx] = W1[(size_t)(k0 + r) * U_ + n0 + tx];
        __syncthreads();
        for (int rr = ty; rr < 32; rr += 8)
            g_w1t[(size_t)(n0 + rr) * D_ + k0 + tx] = __float2half_rn(tile[tx][rr]);
    } else {
        float (*hs)[D_] = (float(*)[D_])sbuf;
        const int pb = bid - NF_BLK - NW_BLK;
        const int u = (pb & 3) * 256 + tid;
        const int b0 = (pb >> 2) * 8;
#pragma unroll
        for (int i = 0; i < 4; i++)
            ((float4*)hs)[tid + i * 256] =
                ((const float4*)(hidden + (size_t)b0 * D_))[tid + i * 256];
        __syncthreads();
        float acc[8];
#pragma unroll
        for (int i = 0; i < 8; i++) acc[i] = 0.f;
#pragma unroll 4
        for (int k = 0; k < D_; k++) {
            float w = W2[(size_t)k * U_ + u];
#pragma unroll
            for (int bb = 0; bb < 8; bb++) acc[bb] += hs[bb][k] * w;
        }
        float bias = W2b[u];
#pragma unroll
        for (int bb = 0; bb < 8; bb++)
            g_projh[(size_t)(b0 + bb) * U_ + u] = acc[bb] + bias;
    }
}

// ---------------------------------------------------------------------------
// score kernel: fp16 mma.sync GEMM + fast-tanh + V-dot epilogue
// (unchanged from R12 — 2 CTAs/SM win)
// ---------------------------------------------------------------------------
__global__ void __launch_bounds__(256, 2)
score_kernel(const float* __restrict__ W1b, const float* __restrict__ Vw) {
    extern __shared__ __align__(1024) char smem[];
    const unsigned sbase = smem_u32(smem);
    const int tid = threadIdx.x;
    const int wid = tid >> 5, lid = tid & 31;
    const int wm = wid & 1, wn = wid >> 1;       // 2 x 4 warp grid, tile 64m x 32n
    const int nq = blockIdx.x;
    const int bt0 = blockIdx.y * 128;
    const int b = bt0 >> 10;
    const int n0 = nq * 128;
    float* shPh = (float*)(smem + OFF_PH);
    float* shV  = (float*)(smem + OFF_V);
    float (*red)[4] = (float(*)[4])(smem + OFF_RED);

    if (tid < 128) {
        shPh[tid] = g_projh[(size_t)b * U_ + n0 + tid] + W1b[n0 + tid];
        shV[tid]  = Vw[n0 + tid];
    }

    unsigned a_src0, a_dst0, b_src0, b_dst0;
    {
        int row = tid >> 3, c16 = tid & 7;
        a_src0 = (unsigned)((bt0 + row) * D_ + c16 * 8);
        a_dst0 = row * 128 + ((c16 ^ (row & 7)) * 16);
        b_src0 = (unsigned)((n0 + row) * D_ + c16 * 8);
        b_dst0 = OFF_BT + row * 128 + ((c16 ^ (row & 7)) * 16);
    }

    const int lrow = lid & 15;
    const int lch  = lid >> 4;
    unsigned abase0, bbase0;
    {
        int row = wm * 64 + lrow;
        abase0 = row * 128 + ((lch ^ (row & 7)) * 16);
        int rowb = wn * 32 + lrow;
        bbase0 = OFF_BT + rowb * 128 + ((lch ^ (rowb & 7)) * 16);
    }

    float Cr[4][4][4];
#pragma unroll
    for (int mt = 0; mt < 4; mt++)
#pragma unroll
        for (int nt = 0; nt < 4; nt++)
#pragma unroll
            for (int j = 0; j < 4; j++) Cr[mt][nt][j] = 0.f;

#pragma unroll
    for (int c = 0; c < 2; c++) {
        const int k0 = c * 64;
        const unsigned stg = sbase + c * STAGE;
#pragma unroll
        for (int i = 0; i < 4; i++)
            cpa16(stg + a_dst0 + i * 4096, g_fhi + k0 + a_src0 + i * 16384);
#pragma unroll
        for (int i = 0; i < 4; i++)
            cpa16(stg + b_dst0 + i * 4096, g_w1t + k0 + b_src0 + i * 16384);
        cpa_commit();
    }

    for (int c = 0; c < 8; c++) {
        asm volatile("cp.async.wait_group 1;" ::: "memory");
        __syncthreads();
        if (c + 2 < 8) {
            const int k0 = (c + 2) * 64;
            const unsigned stg = sbase + ((c + 2) % 3) * STAGE;
#pragma unroll
            for (int i = 0; i < 4; i++)
                cpa16(stg + a_dst0 + i * 4096, g_fhi + k0 + a_src0 + i * 16384);
#pragma unroll
            for (int i = 0; i < 4; i++)
                cpa16(stg + b_dst0 + i * 4096, g_w1t + k0 + b_src0 + i * 16384);
        }
        cpa_commit();

        const unsigned Ab = sbase + (c % 3) * STAGE;
#pragma unroll
        for (int kk = 0; kk < 4; kk++) {
            const unsigned kx = kk << 5;
            unsigned bf[4][2];
#pragma unroll
            for (int np = 0; np < 2; np++) {
                unsigned t0, t1, t2, t3;
                ldsm4(Ab + ((bbase0 + np * 2048) ^ kx), t0, t1, t2, t3);
                bf[np * 2][0] = t0; bf[np * 2][1] = t2;
                bf[np * 2 + 1][0] = t1; bf[np * 2 + 1][1] = t3;
            }
            unsigned ah[4][4];
#pragma unroll
            for (int mt = 0; mt < 4; mt++)
                ldsm4(Ab + ((abase0 + mt * 2048) ^ kx),
                      ah[mt][0], ah[mt][1], ah[mt][2], ah[mt][3]);
#pragma unroll
            for (int mt = 0; mt < 4; mt++)
#pragma unroll
                for (int nt = 0; nt < 4; nt++)
                    mma16816(Cr[mt][nt], ah[mt][0], ah[mt][1], ah[mt][2], ah[mt][3],
                             bf[nt][0], bf[nt][1]);
        }
    }

    float p0[4], p1[4];
#pragma unroll
    for (int mt = 0; mt < 4; mt++) { p0[mt] = 0.f; p1[mt] = 0.f; }
#pragma unroll
    for (int mt = 0; mt < 4; mt++)
#pragma unroll
        for (int nt = 0; nt < 4; nt++) {
            int nc = wn * 32 + nt * 8 + (lid & 3) * 2;
            float ph0 = shPh[nc], ph1 = shPh[nc + 1];
            float v0 = shV[nc], v1 = shV[nc + 1];
            p0[mt] += ftanh(Cr[mt][nt][0] + ph0) * v0
                    + ftanh(Cr[mt][nt][1] + ph1) * v1;
            p1[mt] += ftanh(Cr[mt][nt][2] + ph0) * v0
                    + ftanh(Cr[mt][nt][3] + ph1) * v1;
        }
#pragma unroll
    for (int mt = 0; mt < 4; mt++) {
        p0[mt] += __shfl_xor_sync(0xFFFFFFFFu, p0[mt], 1);
        p0[mt] += __shfl_xor_sync(0xFFFFFFFFu, p0[mt], 2);
        p1[mt] += __shfl_xor_sync(0xFFFFFFFFu, p1[mt], 1);
        p1[mt] += __shfl_xor_sync(0xFFFFFFFFu, p1[mt], 2);
    }
    if ((lid & 3) == 0) {
#pragma unroll
        for (int mt = 0; mt < 4; mt++) {
            int rl = wm * 64 + mt * 16 + (lid >> 2);
            red[rl][wn] = p0[mt];
            red[rl + 8][wn] = p1[mt];
        }
    }
    __syncthreads();
    if (tid < 128) {
        float s = red[tid][0] + red[tid][1] + red[tid][2] + red[tid][3];
        g_lpart[nq][bt0 + tid] = s;
    }
}

// ---------------------------------------------------------------------------
// fused softmax + context kernel: grid (B_, D/128), 1024 threads
// ---------------------------------------------------------------------------
__global__ void __launch_bounds__(1024)
softctx_kernel(const float* __restrict__ Vb, float* __restrict__ out) {
    __shared__ float ws[T_];
    __shared__ float rbuf[32];
    __shared__ float red[32][128];
    const int b = blockIdx.x;
    const int d0 = blockIdx.y * 128;
    const int tid = threadIdx.x;
    const int wid = tid >> 5, lid = tid & 31;

    // ---- softmax over T (each thread owns one logit) ----
    float l = Vb[0];
    {
        const int idx = b * T_ + tid;
#pragma unroll
        for (int q = 0; q < 8; q++) l += g_lpart[q][idx];
    }
    float mx = l;
#pragma unroll
    for (int s = 16; s > 0; s >>= 1) mx = fmaxf(mx, __shfl_xor_sync(~0u, mx, s));
    if (lid == 0) rbuf[wid] = mx;
    __syncthreads();
    if (tid < 32) {
        float m = rbuf[tid];
#pragma unroll
        for (int s = 16; s > 0; s >>= 1) m = fmaxf(m, __shfl_xor_sync(~0u, m, s));
        rbuf[tid] = m;
    }
    __syncthreads();
    mx = rbuf[0];
    float e = __expf(l - mx);
    float ssum = e;
#pragma unroll
    for (int s = 16; s > 0; s >>= 1) ssum += __shfl_xor_sync(~0u, ssum, s);
    __syncthreads();
    if (lid == 0) rbuf[wid] = ssum;
    __syncthreads();
    if (tid < 32) {
        float m = rbuf[tid];
#pragma unroll
        for (int s = 16; s > 0; s >>= 1) m += __shfl_xor_sync(~0u, m, s);
        rbuf[tid] = m;
    }
    __syncthreads();
    const float w = e * __fdividef(1.0f, rbuf[0]);
    ws[tid] = w;
    if (blockIdx.y == 0) out[B_ * D_ + b * T_ + tid] = w;
    __syncthreads();

    // ---- context: 32 T-splits x 32 d-quads ----
    const int dl = tid & 31;
    const int tq = tid >> 5;
    const __half* fb = g_fhi + (size_t)b * T_ * D_ + (size_t)tq * 32 * D_ + d0 + dl * 4;
    const float* wq = ws + tq * 32;
    float4 acc = make_float4(0.f, 0.f, 0.f, 0.f);
#pragma unroll 8
    for (int t = 0; t < 32; t++) {
        float wv = wq[t];
        uint2 h = *(const uint2*)(fb + (size_t)t * D_);
        float2 f0 = __half22float2(*(const __half2*)&h.x);
        float2 f1 = __half22float2(*(const __half2*)&h.y);
        acc.x += wv * f0.x; acc.y += wv * f0.y;
        acc.z += wv * f1.x; acc.w += wv * f1.y;
    }
    red[tq][dl * 4 + 0] = acc.x;
    red[tq][dl * 4 + 1] = acc.y;
    red[tq][dl * 4 + 2] = acc.z;
    red[tq][dl * 4 + 3] = acc.w;
    __syncthreads();
    if (tid < 128) {
        float s = 0.f;
#pragma unroll
        for (int q = 0; q < 32; q++) s += red[q][tid];
        out[b * D_ + d0 + tid] = s;
    }
}

// ---------------------------------------------------------------------------
extern "C" void kernel_launch(void* const* d_in, const int* in_sizes, int n_in,
                              void* d_out, int out_size) {
    const float* feat   = (const float*)d_in[0];
    const float* hidden = (const float*)d_in[1];
    const float* W1w    = (const float*)d_in[2];
    const float* W1b    = (const float*)d_in[3];
    const float* W2w    = (const float*)d_in[4];
    const float* W2b    = (const float*)d_in[5];
    const float* Vw     = (const float*)d_in[6];
    const float* Vb     = (const float*)d_in[7];
    float* out = (float*)d_out;

    static bool attr_set = false;
    if (!attr_set) {
        cudaFuncSetAttribute(score_kernel, cudaFuncAttributeMaxDynamicSharedMemorySize,
                             SMEM_TOTAL);
        attr_set = true;
    }

    prep_kernel<<<NF_BLK + NW_BLK + NP_BLK, 256>>>(feat, W1w, hidden, W2w, W2b);
    score_kernel<<<dim3(8, BT / 128), 256, SMEM_TOTAL>>>(W1b, Vw);
    softctx_kernel<<<dim3(B_, D_ / 128), 1024>>>(Vb, out);
}